// round 1
// baseline (speedup 1.0000x reference)
#include <cuda_runtime.h>
#include <math.h>

#define BB 2
#define SS 2048
#define EE 1024
#define HH 16
#define DH 64
#define MM (BB*SS)   // 4096

// ---------------- scratch (static device globals; no runtime alloc) ----------------
__device__ float g_q[BB*HH*SS*DH];   // [B,H,S,Dh]
__device__ float g_k[BB*HH*SS*DH];
__device__ float g_v[BB*HH*SS*DH];
__device__ float g_att[MM*EE];       // [B,S,E] concat heads
__device__ float g_x[MM*EE];         // residual + proj, pre-LN

// =====================================================================
// Kernel 1: fused QKV projections.  C = X[M,K] * W[N,K]^T + bias
// 64x64 tile, BK=16, 256 threads, 4x4 per thread.
// Output scattered to [B,H,S,Dh] layout.
// =====================================================================
__global__ __launch_bounds__(256)
void qkv_kernel(const float* __restrict__ q_in, const float* __restrict__ k_in,
                const float* __restrict__ v_in,
                const float* __restrict__ wq, const float* __restrict__ bq,
                const float* __restrict__ wk, const float* __restrict__ bk,
                const float* __restrict__ wv, const float* __restrict__ bv)
{
    const int z = blockIdx.z;
    const float* X    = (z == 0) ? q_in : (z == 1) ? k_in : v_in;
    const float* W    = (z == 0) ? wq   : (z == 1) ? wk   : wv;
    const float* bias = (z == 0) ? bq   : (z == 1) ? bk   : bv;
    float* Out        = (z == 0) ? g_q  : (z == 1) ? g_k  : g_v;

    __shared__ float As[16][64];
    __shared__ float Bs[16][64];

    const int tid = threadIdx.x;        // 0..255
    const int tx = tid & 15;
    const int ty = tid >> 4;
    const int m0 = blockIdx.y * 64;
    const int n0 = blockIdx.x * 64;

    const int lrow = tid >> 2;          // 0..63
    const int lcg  = tid & 3;           // 0..3 (16 floats per row via float4)
    const float* aptr = X + (size_t)(m0 + lrow) * EE + lcg * 4;
    const float* bptr = W + (size_t)(n0 + lrow) * EE + lcg * 4;

    float acc[4][4] = {};

    for (int k0 = 0; k0 < EE; k0 += 16) {
        float4 a = *(const float4*)(aptr + k0);
        float4 b = *(const float4*)(bptr + k0);
        __syncthreads();
        As[lcg*4+0][lrow] = a.x; As[lcg*4+1][lrow] = a.y;
        As[lcg*4+2][lrow] = a.z; As[lcg*4+3][lrow] = a.w;
        Bs[lcg*4+0][lrow] = b.x; Bs[lcg*4+1][lrow] = b.y;
        Bs[lcg*4+2][lrow] = b.z; Bs[lcg*4+3][lrow] = b.w;
        __syncthreads();
        #pragma unroll
        for (int kk = 0; kk < 16; kk++) {
            float4 av = *(const float4*)&As[kk][ty*4];
            float4 bv = *(const float4*)&Bs[kk][tx*4];
            float ar[4] = {av.x, av.y, av.z, av.w};
            float br[4] = {bv.x, bv.y, bv.z, bv.w};
            #pragma unroll
            for (int i = 0; i < 4; i++)
                #pragma unroll
                for (int j = 0; j < 4; j++)
                    acc[i][j] += ar[i] * br[j];
        }
    }

    #pragma unroll
    for (int i = 0; i < 4; i++) {
        const int m = m0 + ty*4 + i;
        const int b_ = m >> 11;          // / S
        const int s_ = m & (SS - 1);
        #pragma unroll
        for (int j = 0; j < 4; j++) {
            const int n = n0 + tx*4 + j;
            const int h_ = n >> 6;       // / Dh
            const int d_ = n & 63;
            Out[(((size_t)(b_*HH + h_))*SS + s_)*DH + d_] = acc[i][j] + bias[n];
        }
    }
}

// =====================================================================
// Kernel 2: causal flash attention, fp32.
// Grid: (S/64, B*H).  256 threads (16x16), 4x4 per thread.
// Dynamic smem: Qs/Kt/Vs/Ps each [64][64] = 64 KB.
// =====================================================================
__global__ __launch_bounds__(256)
void attn_kernel()
{
    extern __shared__ float sm[];
    float (*Qs)[64] = (float(*)[64])(sm);
    float (*Kt)[64] = (float(*)[64])(sm + 4096);   // transposed: Kt[d][key]
    float (*Vs)[64] = (float(*)[64])(sm + 8192);
    float (*Ps)[64] = (float(*)[64])(sm + 12288);

    const int bh = blockIdx.y;
    const int qt = blockIdx.x;
    const float* Qg = g_q + (size_t)bh * SS * DH + (size_t)qt * 64 * DH;
    const float* Kg = g_k + (size_t)bh * SS * DH;
    const float* Vg = g_v + (size_t)bh * SS * DH;

    const int tid = threadIdx.x;
    const int tx = tid & 15;
    const int ty = tid >> 4;
    const int ty4 = ty * 4;
    const int tx4 = tx * 4;

    // load Q tile (64 rows x 64 dims)
    #pragma unroll
    for (int it = 0; it < 4; it++) {
        int idx = tid + it * 256;       // 0..1023
        int r = idx >> 4, c4 = idx & 15;
        *(float4*)&Qs[r][c4*4] = *(const float4*)(Qg + r * DH + c4 * 4);
    }

    float O[4][4] = {};
    float mrow[4], lrow[4];
    #pragma unroll
    for (int i = 0; i < 4; i++) { mrow[i] = -1e30f; lrow[i] = 0.f; }

    const float scale = 0.125f;   // 1/sqrt(64)

    for (int t = 0; t <= qt; t++) {
        __syncthreads();   // prev iter done with Kt/Vs/Ps; Q stores visible
        #pragma unroll
        for (int it = 0; it < 4; it++) {
            int idx = tid + it * 256;
            int r = idx >> 4, c4 = idx & 15;
            float4 kv = *(const float4*)(Kg + (size_t)(t*64 + r) * DH + c4 * 4);
            Kt[c4*4+0][r] = kv.x; Kt[c4*4+1][r] = kv.y;
            Kt[c4*4+2][r] = kv.z; Kt[c4*4+3][r] = kv.w;
            *(float4*)&Vs[r][c4*4] = *(const float4*)(Vg + (size_t)(t*64 + r) * DH + c4 * 4);
        }
        __syncthreads();

        // scores: s[i][j] = Q[ty4+i] . K[tx4+j]
        float sc[4][4] = {};
        #pragma unroll 8
        for (int kk = 0; kk < 64; kk++) {
            float4 kvec = *(const float4*)&Kt[kk][tx4];
            float kr[4] = {kvec.x, kvec.y, kvec.z, kvec.w};
            #pragma unroll
            for (int i = 0; i < 4; i++) {
                float qv = Qs[ty4 + i][kk];
                #pragma unroll
                for (int j = 0; j < 4; j++) sc[i][j] += qv * kr[j];
            }
        }

        // scale + causal mask (only diagonal tile has masked entries)
        if (t == qt) {
            #pragma unroll
            for (int i = 0; i < 4; i++) {
                int qi = qt*64 + ty4 + i;
                #pragma unroll
                for (int j = 0; j < 4; j++) {
                    int kj = t*64 + tx4 + j;
                    sc[i][j] = (kj > qi) ? -1e30f : sc[i][j] * scale;
                }
            }
        } else {
            #pragma unroll
            for (int i = 0; i < 4; i++)
                #pragma unroll
                for (int j = 0; j < 4; j++) sc[i][j] *= scale;
        }

        // online softmax per row (row group = 16 lanes sharing ty)
        #pragma unroll
        for (int i = 0; i < 4; i++) {
            float mt = fmaxf(fmaxf(sc[i][0], sc[i][1]), fmaxf(sc[i][2], sc[i][3]));
            #pragma unroll
            for (int off = 8; off; off >>= 1)
                mt = fmaxf(mt, __shfl_xor_sync(0xffffffffu, mt, off));
            float mn = fmaxf(mrow[i], mt);
            float alpha = __expf(mrow[i] - mn);
            mrow[i] = mn;
            float psum = 0.f;
            #pragma unroll
            for (int j = 0; j < 4; j++) {
                sc[i][j] = __expf(sc[i][j] - mn);
                psum += sc[i][j];
            }
            #pragma unroll
            for (int off = 8; off; off >>= 1)
                psum += __shfl_xor_sync(0xffffffffu, psum, off);
            lrow[i] = lrow[i] * alpha + psum;
            #pragma unroll
            for (int j = 0; j < 4; j++) O[i][j] *= alpha;
        }

        // stage P to smem
        #pragma unroll
        for (int i = 0; i < 4; i++)
            *(float4*)&Ps[ty4 + i][tx4] = make_float4(sc[i][0], sc[i][1], sc[i][2], sc[i][3]);
        __syncthreads();

        // O += P @ V
        #pragma unroll 8
        for (int c = 0; c < 64; c++) {
            float4 vvec = *(const float4*)&Vs[c][tx4];
            float vr[4] = {vvec.x, vvec.y, vvec.z, vvec.w};
            #pragma unroll
            for (int i = 0; i < 4; i++) {
                float p = Ps[ty4 + i][c];
                #pragma unroll
                for (int j = 0; j < 4; j++) O[i][j] += p * vr[j];
            }
        }
    }

    // write ctx to concat-heads layout
    const int b_ = bh >> 4;   // / H
    const int h_ = bh & 15;
    #pragma unroll
    for (int i = 0; i < 4; i++) {
        const int srow = qt*64 + ty4 + i;
        const float inv = 1.0f / lrow[i];
        float4 o = make_float4(O[i][0]*inv, O[i][1]*inv, O[i][2]*inv, O[i][3]*inv);
        *(float4*)(g_att + ((size_t)(b_*SS + srow))*EE + h_*64 + tx4) = o;
    }
}

// =====================================================================
// Kernel 3: output projection + residual.  g_x = att @ out_w^T + out_b + query
// =====================================================================
__global__ __launch_bounds__(256)
void proj_kernel(const float* __restrict__ query,
                 const float* __restrict__ W, const float* __restrict__ bias)
{
    __shared__ float As[16][64];
    __shared__ float Bs[16][64];

    const int tid = threadIdx.x;
    const int tx = tid & 15;
    const int ty = tid >> 4;
    const int m0 = blockIdx.y * 64;
    const int n0 = blockIdx.x * 64;

    const int lrow = tid >> 2;
    const int lcg  = tid & 3;
    const float* aptr = g_att + (size_t)(m0 + lrow) * EE + lcg * 4;
    const float* bptr = W     + (size_t)(n0 + lrow) * EE + lcg * 4;

    float acc[4][4] = {};

    for (int k0 = 0; k0 < EE; k0 += 16) {
        float4 a = *(const float4*)(aptr + k0);
        float4 b = *(const float4*)(bptr + k0);
        __syncthreads();
        As[lcg*4+0][lrow] = a.x; As[lcg*4+1][lrow] = a.y;
        As[lcg*4+2][lrow] = a.z; As[lcg*4+3][lrow] = a.w;
        Bs[lcg*4+0][lrow] = b.x; Bs[lcg*4+1][lrow] = b.y;
        Bs[lcg*4+2][lrow] = b.z; Bs[lcg*4+3][lrow] = b.w;
        __syncthreads();
        #pragma unroll
        for (int kk = 0; kk < 16; kk++) {
            float4 av = *(const float4*)&As[kk][ty*4];
            float4 bv = *(const float4*)&Bs[kk][tx*4];
            float ar[4] = {av.x, av.y, av.z, av.w};
            float br[4] = {bv.x, bv.y, bv.z, bv.w};
            #pragma unroll
            for (int i = 0; i < 4; i++)
                #pragma unroll
                for (int j = 0; j < 4; j++)
                    acc[i][j] += ar[i] * br[j];
        }
    }

    #pragma unroll
    for (int i = 0; i < 4; i++) {
        const int m = m0 + ty*4 + i;
        #pragma unroll
        for (int j = 0; j < 4; j++) {
            const int n = n0 + tx*4 + j;
            g_x[(size_t)m*EE + n] = acc[i][j] + bias[n] + query[(size_t)m*EE + n];
        }
    }
}

// =====================================================================
// Kernel 4: LayerNorm over E=1024.  One block (256 threads) per row.
// =====================================================================
__global__ __launch_bounds__(256)
void ln_kernel(const float* __restrict__ gamma, const float* __restrict__ beta,
               float* __restrict__ out)
{
    const int row = blockIdx.x;
    const float* x = g_x + (size_t)row * EE;
    const int tid = threadIdx.x;

    float4 v = *(const float4*)(x + tid * 4);
    float s = v.x + v.y + v.z + v.w;
    float q = v.x*v.x + v.y*v.y + v.z*v.z + v.w*v.w;
    #pragma unroll
    for (int off = 16; off; off >>= 1) {
        s += __shfl_xor_sync(0xffffffffu, s, off);
        q += __shfl_xor_sync(0xffffffffu, q, off);
    }
    __shared__ float ssum[8], ssq[8], stats[2];
    const int w = tid >> 5;
    if ((tid & 31) == 0) { ssum[w] = s; ssq[w] = q; }
    __syncthreads();
    if (tid < 32) {
        float s2 = (tid < 8) ? ssum[tid] : 0.f;
        float q2 = (tid < 8) ? ssq[tid]  : 0.f;
        #pragma unroll
        for (int off = 4; off; off >>= 1) {
            s2 += __shfl_xor_sync(0xffffffffu, s2, off);
            q2 += __shfl_xor_sync(0xffffffffu, q2, off);
        }
        if (tid == 0) {
            float mu = s2 * (1.0f / EE);
            float var = q2 * (1.0f / EE) - mu * mu;
            stats[0] = mu;
            stats[1] = rsqrtf(var + 1e-5f);
        }
    }
    __syncthreads();
    const float mu = stats[0];
    const float r  = stats[1];

    float4 gv = *(const float4*)(gamma + tid * 4);
    float4 bv = *(const float4*)(beta  + tid * 4);
    float4 o;
    o.x = (v.x - mu) * r * gv.x + bv.x;
    o.y = (v.y - mu) * r * gv.y + bv.y;
    o.z = (v.z - mu) * r * gv.z + bv.z;
    o.w = (v.w - mu) * r * gv.w + bv.w;
    *(float4*)(out + (size_t)row * EE + tid * 4) = o;
}

// =====================================================================
extern "C" void kernel_launch(void* const* d_in, const int* in_sizes, int n_in,
                              void* d_out, int out_size)
{
    (void)in_sizes; (void)n_in; (void)out_size;
    const float* query = (const float*)d_in[0];
    const float* key_i = (const float*)d_in[1];
    const float* value = (const float*)d_in[2];
    // d_in[3] = mask (causal; hard-coded in kernel)
    const float* Wq_w = (const float*)d_in[4];
    const float* Wq_b = (const float*)d_in[5];
    const float* Wk_w = (const float*)d_in[6];
    const float* Wk_b = (const float*)d_in[7];
    const float* Wv_w = (const float*)d_in[8];
    const float* Wv_b = (const float*)d_in[9];
    const float* out_w = (const float*)d_in[10];
    const float* out_b = (const float*)d_in[11];
    const float* ln_g = (const float*)d_in[12];
    const float* ln_b = (const float*)d_in[13];
    float* out = (float*)d_out;

    // 1. QKV projections
    dim3 g1(EE / 64, MM / 64, 3);
    qkv_kernel<<<g1, 256>>>(query, key_i, value,
                            Wq_w, Wq_b, Wk_w, Wk_b, Wv_w, Wv_b);

    // 2. causal flash attention (64 KB dynamic smem)
    const int smem_attn = 4 * 64 * 64 * (int)sizeof(float);   // 65536
    cudaFuncSetAttribute(attn_kernel, cudaFuncAttributeMaxDynamicSharedMemorySize, smem_attn);
    attn_kernel<<<dim3(SS / 64, BB * HH), 256, smem_attn>>>();

    // 3. output projection + residual
    dim3 g3(EE / 64, MM / 64);
    proj_kernel<<<g3, 256>>>(query, out_w, out_b);

    // 4. LayerNorm
    ln_kernel<<<MM, 256>>>(ln_g, ln_b, out);
}

// round 3
// speedup vs baseline: 1.3143x; 1.3143x over previous
#include <cuda_runtime.h>
#include <cstdint>
#include <math.h>

#define BB 2
#define SS 2048
#define EE 1024
#define HH 16
#define DH 64
#define MM (BB*SS)   // 4096

// ---------------- scratch (static device globals; no runtime alloc) ----------------
__device__ float g_q[BB*HH*SS*DH];   // [B,H,S,Dh]
__device__ float g_k[BB*HH*SS*DH];
__device__ float g_v[BB*HH*SS*DH];
__device__ float g_att[MM*EE];       // [B,S,E] concat heads
__device__ float g_x[MM*EE];         // residual + proj, pre-LN

// =====================================================================
// tf32 helpers
// =====================================================================
__device__ __forceinline__ float tf32_hi(float x){
    return __uint_as_float(__float_as_uint(x) & 0xFFFFE000u);
}
// swizzled column for SMEM tile [16][128]: conflict-free for both the
// staging stores and the m16n8k8 fragment load patterns.
__device__ __forceinline__ int swc(int m, int k){
    return m ^ ((((k & 3) ^ (k >> 2)) & 3) << 3);
}
__device__ __forceinline__ void mma_tf32(float d[4], const float a[4], const float b[2]){
    asm volatile(
        "mma.sync.aligned.m16n8k8.row.col.f32.tf32.tf32.f32 "
        "{%0,%1,%2,%3}, {%4,%5,%6,%7}, {%8,%9}, {%0,%1,%2,%3};"
        : "+f"(d[0]), "+f"(d[1]), "+f"(d[2]), "+f"(d[3])
        : "r"(__float_as_uint(a[0])), "r"(__float_as_uint(a[1])),
          "r"(__float_as_uint(a[2])), "r"(__float_as_uint(a[3])),
          "r"(__float_as_uint(b[0])), "r"(__float_as_uint(b[1])));
}

// =====================================================================
// 128x128x(K=EE) tf32x3 GEMM core.  C = A[128,K] * B[128,K]^T
// 8 warps: wm = w&1 (2 M-warps of 64 rows), wn = w>>1 (4 N-warps of 32 cols).
// SMEM stage (8192 floats = 32KB): A_hi | A_lo | B_hi | B_lo, each [16][128],
// element (k,m) at k*128 + swc(m,k). Double buffered -> 64KB.
// =====================================================================
__device__ __forceinline__ void stage_store(float* buf, int m, int kq,
                                            float4 va0, float4 va1,
                                            float4 vb0, float4 vb1)
{
    float* Ah = buf;
    float* Al = buf + 2048;
    float* Bh = buf + 4096;
    float* Bl = buf + 6144;
    const float* a0 = (const float*)&va0;
    const float* a1 = (const float*)&va1;
    const float* b0 = (const float*)&vb0;
    const float* b1 = (const float*)&vb1;
    #pragma unroll
    for (int j = 0; j < 4; j++) {
        {
            const int k = kq + j;
            const int c = k * 128 + swc(m, k);
            float x = a0[j], h = tf32_hi(x);
            Ah[c] = h; Al[c] = x - h;
            float y = b0[j], g = tf32_hi(y);
            Bh[c] = g; Bl[c] = y - g;
        }
        {
            const int k = kq + 4 + j;
            const int c = k * 128 + swc(m, k);
            float x = a1[j], h = tf32_hi(x);
            Ah[c] = h; Al[c] = x - h;
            float y = b1[j], g = tf32_hi(y);
            Bh[c] = g; Bl[c] = y - g;
        }
    }
}

__device__ __forceinline__ void tile_compute(const float* buf, int wm, int wn,
                                             int lane, float d[4][4][4])
{
    const int qrow = lane >> 2;
    const int qk   = lane & 3;
    const float* Ah = buf;
    const float* Al = buf + 2048;
    const float* Bh = buf + 4096;
    const float* Bl = buf + 6144;

    #pragma unroll
    for (int s = 0; s < 2; s++) {
        const int k0 = s * 8 + qk;
        const int k1 = k0 + 4;
        float ah[4][4], al[4][4], bh[4][2], bl[4][2];
        #pragma unroll
        for (int mt = 0; mt < 4; mt++) {
            const int m = wm * 64 + mt * 16 + qrow;
            const int i00 = k0 * 128 + swc(m,     k0);
            const int i01 = k0 * 128 + swc(m + 8, k0);
            const int i10 = k1 * 128 + swc(m,     k1);
            const int i11 = k1 * 128 + swc(m + 8, k1);
            ah[mt][0] = Ah[i00]; ah[mt][1] = Ah[i01];
            ah[mt][2] = Ah[i10]; ah[mt][3] = Ah[i11];
            al[mt][0] = Al[i00]; al[mt][1] = Al[i01];
            al[mt][2] = Al[i10]; al[mt][3] = Al[i11];
        }
        #pragma unroll
        for (int nt = 0; nt < 4; nt++) {
            const int n = wn * 32 + nt * 8 + qrow;
            const int i0 = k0 * 128 + swc(n, k0);
            const int i1 = k1 * 128 + swc(n, k1);
            bh[nt][0] = Bh[i0]; bh[nt][1] = Bh[i1];
            bl[nt][0] = Bl[i0]; bl[nt][1] = Bl[i1];
        }
        #pragma unroll
        for (int mt = 0; mt < 4; mt++)
            #pragma unroll
            for (int nt = 0; nt < 4; nt++) {
                mma_tf32(d[mt][nt], ah[mt], bh[nt]);
                mma_tf32(d[mt][nt], ah[mt], bl[nt]);
                mma_tf32(d[mt][nt], al[mt], bh[nt]);
            }
    }
}

__device__ __forceinline__ void run_gemm(const float* __restrict__ A,
                                         const float* __restrict__ B,
                                         float* sm, int tid, float d[4][4][4])
{
    const int lane = tid & 31;
    const int w    = tid >> 5;
    const int wm   = w & 1;
    const int wn   = w >> 1;
    const int m_st = tid >> 1;           // 0..127
    const int kq   = (tid & 1) * 8;      // 0 or 8

    const float* Ag = A + (size_t)m_st * EE + kq;
    const float* Bg = B + (size_t)m_st * EE + kq;

    float4 va0 = *(const float4*)(Ag);
    float4 va1 = *(const float4*)(Ag + 4);
    float4 vb0 = *(const float4*)(Bg);
    float4 vb1 = *(const float4*)(Bg + 4);
    stage_store(sm, m_st, kq, va0, va1, vb0, vb1);
    __syncthreads();

    for (int kt = 0; kt < EE / 16; kt++) {
        const float* cur = sm + (kt & 1) * 8192;
        if (kt < EE / 16 - 1) {
            const int off = (kt + 1) * 16;
            va0 = *(const float4*)(Ag + off);
            va1 = *(const float4*)(Ag + off + 4);
            vb0 = *(const float4*)(Bg + off);
            vb1 = *(const float4*)(Bg + off + 4);
        }
        tile_compute(cur, wm, wn, lane, d);
        if (kt < EE / 16 - 1)
            stage_store(sm + ((kt + 1) & 1) * 8192, m_st, kq, va0, va1, vb0, vb1);
        __syncthreads();
    }
}

// =====================================================================
// Kernel 1: fused QKV projections (tf32x3 mma.sync).
// grid (8, 32, 3), 256 threads, 64KB dyn smem.
// =====================================================================
__global__ __launch_bounds__(256, 1)
void qkv_mma(const float* __restrict__ qin, const float* __restrict__ kin,
             const float* __restrict__ vin,
             const float* __restrict__ wq, const float* __restrict__ bq,
             const float* __restrict__ wk, const float* __restrict__ bk,
             const float* __restrict__ wv, const float* __restrict__ bv)
{
    extern __shared__ float smf[];
    const int z = blockIdx.z;
    const float* A    = (z == 0) ? qin : (z == 1) ? kin : vin;
    const float* W    = (z == 0) ? wq  : (z == 1) ? wk  : wv;
    const float* bias = (z == 0) ? bq  : (z == 1) ? bk  : bv;
    float* Out        = (z == 0) ? g_q : (z == 1) ? g_k : g_v;

    const int m0 = blockIdx.y * 128;
    const int n0 = blockIdx.x * 128;
    const int tid = threadIdx.x;

    float d[4][4][4] = {};
    run_gemm(A + (size_t)m0 * EE, W + (size_t)n0 * EE, smf, tid, d);

    const int lane = tid & 31;
    const int w    = tid >> 5;
    const int wm   = w & 1;
    const int wn   = w >> 1;
    const int qrow = lane >> 2;
    const int qc   = (lane & 3) * 2;

    #pragma unroll
    for (int mt = 0; mt < 4; mt++) {
        const int gm0 = m0 + wm * 64 + mt * 16 + qrow;
        #pragma unroll
        for (int nt = 0; nt < 4; nt++) {
            const int gn = n0 + wn * 32 + nt * 8 + qc;
            const int h  = gn >> 6;
            const int dh = gn & 63;
            const float bx = bias[gn], by = bias[gn + 1];
            #pragma unroll
            for (int r = 0; r < 2; r++) {
                const int gm = gm0 + r * 8;
                const int b_ = gm >> 11;
                const int s_ = gm & (SS - 1);
                float2 o = make_float2(d[mt][nt][r * 2 + 0] + bx,
                                       d[mt][nt][r * 2 + 1] + by);
                *(float2*)(Out + (((size_t)(b_ * HH + h)) * SS + s_) * DH + dh) = o;
            }
        }
    }
}

// =====================================================================
// Kernel 3: output projection + residual (tf32x3 mma.sync).
// =====================================================================
__global__ __launch_bounds__(256, 1)
void proj_mma(const float* __restrict__ query,
              const float* __restrict__ W, const float* __restrict__ bias)
{
    extern __shared__ float smf[];
    const int m0 = blockIdx.y * 128;
    const int n0 = blockIdx.x * 128;
    const int tid = threadIdx.x;

    float d[4][4][4] = {};
    run_gemm(g_att + (size_t)m0 * EE, W + (size_t)n0 * EE, smf, tid, d);

    const int lane = tid & 31;
    const int w    = tid >> 5;
    const int wm   = w & 1;
    const int wn   = w >> 1;
    const int qrow = lane >> 2;
    const int qc   = (lane & 3) * 2;

    #pragma unroll
    for (int mt = 0; mt < 4; mt++) {
        const int gm0 = m0 + wm * 64 + mt * 16 + qrow;
        #pragma unroll
        for (int nt = 0; nt < 4; nt++) {
            const int gn = n0 + wn * 32 + nt * 8 + qc;
            const float bx = bias[gn], by = bias[gn + 1];
            #pragma unroll
            for (int r = 0; r < 2; r++) {
                const int gm = gm0 + r * 8;
                const float* qp = query + (size_t)gm * EE + gn;
                float2 o = make_float2(d[mt][nt][r * 2 + 0] + bx + qp[0],
                                       d[mt][nt][r * 2 + 1] + by + qp[1]);
                *(float2*)(g_x + (size_t)gm * EE + gn) = o;
            }
        }
    }
}

// =====================================================================
// Kernel 2: causal flash attention, fp32 SIMT (known-good from R1).
// =====================================================================
__global__ __launch_bounds__(256)
void attn_kernel()
{
    extern __shared__ float sm[];
    float (*Qs)[64] = (float(*)[64])(sm);
    float (*Kt)[64] = (float(*)[64])(sm + 4096);
    float (*Vs)[64] = (float(*)[64])(sm + 8192);
    float (*Ps)[64] = (float(*)[64])(sm + 12288);

    const int bh = blockIdx.y;
    const int qt = blockIdx.x;
    const float* Qg = g_q + (size_t)bh * SS * DH + (size_t)qt * 64 * DH;
    const float* Kg = g_k + (size_t)bh * SS * DH;
    const float* Vg = g_v + (size_t)bh * SS * DH;

    const int tid = threadIdx.x;
    const int tx = tid & 15;
    const int ty = tid >> 4;
    const int ty4 = ty * 4;
    const int tx4 = tx * 4;

    #pragma unroll
    for (int it = 0; it < 4; it++) {
        int idx = tid + it * 256;
        int r = idx >> 4, c4 = idx & 15;
        *(float4*)&Qs[r][c4*4] = *(const float4*)(Qg + r * DH + c4 * 4);
    }

    float O[4][4] = {};
    float mrow[4], lrow[4];
    #pragma unroll
    for (int i = 0; i < 4; i++) { mrow[i] = -1e30f; lrow[i] = 0.f; }

    const float scale = 0.125f;

    for (int t = 0; t <= qt; t++) {
        __syncthreads();
        #pragma unroll
        for (int it = 0; it < 4; it++) {
            int idx = tid + it * 256;
            int r = idx >> 4, c4 = idx & 15;
            float4 kv = *(const float4*)(Kg + (size_t)(t*64 + r) * DH + c4 * 4);
            Kt[c4*4+0][r] = kv.x; Kt[c4*4+1][r] = kv.y;
            Kt[c4*4+2][r] = kv.z; Kt[c4*4+3][r] = kv.w;
            *(float4*)&Vs[r][c4*4] = *(const float4*)(Vg + (size_t)(t*64 + r) * DH + c4 * 4);
        }
        __syncthreads();

        float sc[4][4] = {};
        #pragma unroll 8
        for (int kk = 0; kk < 64; kk++) {
            float4 kvec = *(const float4*)&Kt[kk][tx4];
            float kr[4] = {kvec.x, kvec.y, kvec.z, kvec.w};
            #pragma unroll
            for (int i = 0; i < 4; i++) {
                float qv = Qs[ty4 + i][kk];
                #pragma unroll
                for (int j = 0; j < 4; j++) sc[i][j] += qv * kr[j];
            }
        }

        if (t == qt) {
            #pragma unroll
            for (int i = 0; i < 4; i++) {
                int qi = qt*64 + ty4 + i;
                #pragma unroll
                for (int j = 0; j < 4; j++) {
                    int kj = t*64 + tx4 + j;
                    sc[i][j] = (kj > qi) ? -1e30f : sc[i][j] * scale;
                }
            }
        } else {
            #pragma unroll
            for (int i = 0; i < 4; i++)
                #pragma unroll
                for (int j = 0; j < 4; j++) sc[i][j] *= scale;
        }

        #pragma unroll
        for (int i = 0; i < 4; i++) {
            float mt = fmaxf(fmaxf(sc[i][0], sc[i][1]), fmaxf(sc[i][2], sc[i][3]));
            #pragma unroll
            for (int off = 8; off; off >>= 1)
                mt = fmaxf(mt, __shfl_xor_sync(0xffffffffu, mt, off));
            float mn = fmaxf(mrow[i], mt);
            float alpha = __expf(mrow[i] - mn);
            mrow[i] = mn;
            float psum = 0.f;
            #pragma unroll
            for (int j = 0; j < 4; j++) {
                sc[i][j] = __expf(sc[i][j] - mn);
                psum += sc[i][j];
            }
            #pragma unroll
            for (int off = 8; off; off >>= 1)
                psum += __shfl_xor_sync(0xffffffffu, psum, off);
            lrow[i] = lrow[i] * alpha + psum;
            #pragma unroll
            for (int j = 0; j < 4; j++) O[i][j] *= alpha;
        }

        #pragma unroll
        for (int i = 0; i < 4; i++)
            *(float4*)&Ps[ty4 + i][tx4] = make_float4(sc[i][0], sc[i][1], sc[i][2], sc[i][3]);
        __syncthreads();

        #pragma unroll 8
        for (int c = 0; c < 64; c++) {
            float4 vvec = *(const float4*)&Vs[c][tx4];
            float vr[4] = {vvec.x, vvec.y, vvec.z, vvec.w};
            #pragma unroll
            for (int i = 0; i < 4; i++) {
                float p = Ps[ty4 + i][c];
                #pragma unroll
                for (int j = 0; j < 4; j++) O[i][j] += p * vr[j];
            }
        }
    }

    const int b_ = bh >> 4;
    const int h_ = bh & 15;
    #pragma unroll
    for (int i = 0; i < 4; i++) {
        const int srow = qt*64 + ty4 + i;
        const float inv = 1.0f / lrow[i];
        float4 o = make_float4(O[i][0]*inv, O[i][1]*inv, O[i][2]*inv, O[i][3]*inv);
        *(float4*)(g_att + ((size_t)(b_*SS + srow))*EE + h_*64 + tx4) = o;
    }
}

// =====================================================================
// Kernel 4: LayerNorm (unchanged).
// =====================================================================
__global__ __launch_bounds__(256)
void ln_kernel(const float* __restrict__ gamma, const float* __restrict__ beta,
               float* __restrict__ out)
{
    const int row = blockIdx.x;
    const float* x = g_x + (size_t)row * EE;
    const int tid = threadIdx.x;

    float4 v = *(const float4*)(x + tid * 4);
    float s = v.x + v.y + v.z + v.w;
    float q = v.x*v.x + v.y*v.y + v.z*v.z + v.w*v.w;
    #pragma unroll
    for (int off = 16; off; off >>= 1) {
        s += __shfl_xor_sync(0xffffffffu, s, off);
        q += __shfl_xor_sync(0xffffffffu, q, off);
    }
    __shared__ float ssum[8], ssq[8], stats[2];
    const int w = tid >> 5;
    if ((tid & 31) == 0) { ssum[w] = s; ssq[w] = q; }
    __syncthreads();
    if (tid < 32) {
        float s2 = (tid < 8) ? ssum[tid] : 0.f;
        float q2 = (tid < 8) ? ssq[tid]  : 0.f;
        #pragma unroll
        for (int off = 4; off; off >>= 1) {
            s2 += __shfl_xor_sync(0xffffffffu, s2, off);
            q2 += __shfl_xor_sync(0xffffffffu, q2, off);
        }
        if (tid == 0) {
            float mu = s2 * (1.0f / EE);
            float var = q2 * (1.0f / EE) - mu * mu;
            stats[0] = mu;
            stats[1] = rsqrtf(var + 1e-5f);
        }
    }
    __syncthreads();
    const float mu = stats[0];
    const float r  = stats[1];

    float4 gv = *(const float4*)(gamma + tid * 4);
    float4 bv = *(const float4*)(beta  + tid * 4);
    float4 o;
    o.x = (v.x - mu) * r * gv.x + bv.x;
    o.y = (v.y - mu) * r * gv.y + bv.y;
    o.z = (v.z - mu) * r * gv.z + bv.z;
    o.w = (v.w - mu) * r * gv.w + bv.w;
    *(float4*)(out + (size_t)row * EE + tid * 4) = o;
}

// =====================================================================
extern "C" void kernel_launch(void* const* d_in, const int* in_sizes, int n_in,
                              void* d_out, int out_size)
{
    (void)in_sizes; (void)n_in; (void)out_size;
    const float* query = (const float*)d_in[0];
    const float* key_i = (const float*)d_in[1];
    const float* value = (const float*)d_in[2];
    // d_in[3] = mask (causal; hard-coded in kernel)
    const float* Wq_w = (const float*)d_in[4];
    const float* Wq_b = (const float*)d_in[5];
    const float* Wk_w = (const float*)d_in[6];
    const float* Wk_b = (const float*)d_in[7];
    const float* Wv_w = (const float*)d_in[8];
    const float* Wv_b = (const float*)d_in[9];
    const float* out_w = (const float*)d_in[10];
    const float* out_b = (const float*)d_in[11];
    const float* ln_g = (const float*)d_in[12];
    const float* ln_b = (const float*)d_in[13];
    float* out = (float*)d_out;

    const int SMEM_GEMM = 2 * 8192 * (int)sizeof(float);   // 65536
    cudaFuncSetAttribute(qkv_mma,  cudaFuncAttributeMaxDynamicSharedMemorySize, SMEM_GEMM);
    cudaFuncSetAttribute(proj_mma, cudaFuncAttributeMaxDynamicSharedMemorySize, SMEM_GEMM);

    // 1. QKV projections (tf32x3 mma.sync)
    qkv_mma<<<dim3(EE/128, MM/128, 3), 256, SMEM_GEMM>>>(query, key_i, value,
                                                         Wq_w, Wq_b, Wk_w, Wk_b, Wv_w, Wv_b);

    // 2. causal flash attention (SIMT fp32, 64 KB dynamic smem)
    const int smem_attn = 4 * 64 * 64 * (int)sizeof(float);
    cudaFuncSetAttribute(attn_kernel, cudaFuncAttributeMaxDynamicSharedMemorySize, smem_attn);
    attn_kernel<<<dim3(SS / 64, BB * HH), 256, smem_attn>>>();

    // 3. output projection + residual (tf32x3 mma.sync)
    proj_mma<<<dim3(EE/128, MM/128), 256, SMEM_GEMM>>>(query, out_w, out_b);

    // 4. LayerNorm
    ln_kernel<<<MM, 256>>>(ln_g, ln_b, out);
}

// round 4
// speedup vs baseline: 2.1362x; 1.6253x over previous
#include <cuda_runtime.h>
#include <cuda_bf16.h>
#include <cstdint>
#include <math.h>

#define BB 2
#define SS 2048
#define EE 1024
#define HH 16
#define DH 64
#define MM (BB*SS)   // 4096

// ---------------- scratch (static device globals; no runtime alloc) ----------------
__device__ float g_q[BB*HH*SS*DH];   // [B,H,S,Dh]
__device__ float g_k[BB*HH*SS*DH];
__device__ float g_v[BB*HH*SS*DH];
__device__ float g_att[MM*EE];       // [B,S,E] concat heads
__device__ float g_x[MM*EE];         // residual + proj, pre-LN

// =====================================================================
// bf16 helpers
// =====================================================================
__device__ __forceinline__ void mma_bf16(float d[4], const uint32_t a[4], const uint32_t b[2]){
    asm volatile(
        "mma.sync.aligned.m16n8k16.row.col.f32.bf16.bf16.f32 "
        "{%0,%1,%2,%3}, {%4,%5,%6,%7}, {%8,%9}, {%0,%1,%2,%3};"
        : "+f"(d[0]), "+f"(d[1]), "+f"(d[2]), "+f"(d[3])
        : "r"(a[0]), "r"(a[1]), "r"(a[2]), "r"(a[3]),
          "r"(b[0]), "r"(b[1]));
}
// split (x,y) into bf16x2 hi word + bf16x2 lo word (lo = exact remainder)
__device__ __forceinline__ void bsplit2(float x, float y, uint32_t& h, uint32_t& l){
    __nv_bfloat162 hh = __floats2bfloat162_rn(x, y);
    float lx = x - __bfloat162float(hh.x);
    float ly = y - __bfloat162float(hh.y);
    __nv_bfloat162 ll = __floats2bfloat162_rn(lx, ly);
    h = *(uint32_t*)&hh;
    l = *(uint32_t*)&ll;
}
__device__ __forceinline__ uint32_t bpack(float x, float y){
    __nv_bfloat162 hh = __floats2bfloat162_rn(x, y);
    return *(uint32_t*)&hh;
}

// =====================================================================
// 128x128xK GEMM core, bf16 3-term split.  C = A[128,K] * B[128,K]^T
// 8 warps: wm = w&1 (64 rows), wn = w>>1 (32 cols). BK=16 per stage.
// Stage (16KB): Ah|Al|Bh|Bl, each [128 rows][8 words] bf16x2 along k,
// word = row*8 + (kp ^ (row&4)). Double buffered.
// =====================================================================
__device__ __forceinline__ void g_stage(uint32_t* buf, int m, int kh,
                                        float4 a0, float4 a1, float4 b0, float4 b1)
{
    const float* af = (const float*)&a0;   // a0,a1 contiguous? build arrays
    float av[8] = {a0.x,a0.y,a0.z,a0.w,a1.x,a1.y,a1.z,a1.w};
    float bv[8] = {b0.x,b0.y,b0.z,b0.w,b1.x,b1.y,b1.z,b1.w};
    (void)af;
    const int sw = m & 4;
    #pragma unroll
    for (int j = 0; j < 4; j++) {
        const int kp = kh*4 + j;
        const int wd = m*8 + (kp ^ sw);
        uint32_t h, l;
        bsplit2(av[2*j], av[2*j+1], h, l);
        buf[wd] = h; buf[1024 + wd] = l;
        bsplit2(bv[2*j], bv[2*j+1], h, l);
        buf[2048 + wd] = h; buf[3072 + wd] = l;
    }
}

__device__ __forceinline__ void g_tile(const uint32_t* buf, int wm, int wn,
                                       int lane, float d[4][4][4])
{
    const int qrow = lane >> 2;
    const int qk   = lane & 3;
    const int sw   = qrow & 4;
    const int kp0  = qk ^ sw;
    const int kp1  = (qk + 4) ^ sw;

    uint32_t ah[4][4], al[4][4], bh[4][2], bl[4][2];
    #pragma unroll
    for (int mt = 0; mt < 4; mt++) {
        const int m = wm*64 + mt*16 + qrow;
        const int w0 = m*8 + kp0;
        const int w1 = (m+8)*8 + kp0;
        const int w2 = m*8 + kp1;
        const int w3 = (m+8)*8 + kp1;
        ah[mt][0] = buf[w0]; ah[mt][1] = buf[w1]; ah[mt][2] = buf[w2]; ah[mt][3] = buf[w3];
        al[mt][0] = buf[1024+w0]; al[mt][1] = buf[1024+w1];
        al[mt][2] = buf[1024+w2]; al[mt][3] = buf[1024+w3];
    }
    #pragma unroll
    for (int nt = 0; nt < 4; nt++) {
        const int n = wn*32 + nt*8 + qrow;
        const int w0 = n*8 + kp0;
        const int w1 = n*8 + kp1;
        bh[nt][0] = buf[2048+w0]; bh[nt][1] = buf[2048+w1];
        bl[nt][0] = buf[3072+w0]; bl[nt][1] = buf[3072+w1];
    }
    #pragma unroll
    for (int mt = 0; mt < 4; mt++)
        #pragma unroll
        for (int nt = 0; nt < 4; nt++) {
            mma_bf16(d[mt][nt], ah[mt], bh[nt]);
            mma_bf16(d[mt][nt], ah[mt], bl[nt]);
            mma_bf16(d[mt][nt], al[mt], bh[nt]);
        }
}

__device__ __forceinline__ void run_gemm(const float* __restrict__ A,
                                         const float* __restrict__ B,
                                         uint32_t* sm, int tid, float d[4][4][4])
{
    const int lane = tid & 31;
    const int w    = tid >> 5;
    const int wm   = w & 1;
    const int wn   = w >> 1;
    const int m_st = tid >> 1;           // 0..127
    const int kh   = tid & 1;            // half: words 4kh..4kh+3 (floats 8kh..)

    const float* Ag = A + (size_t)m_st * EE + kh * 8;
    const float* Bg = B + (size_t)m_st * EE + kh * 8;

    float4 va0 = *(const float4*)(Ag);
    float4 va1 = *(const float4*)(Ag + 4);
    float4 vb0 = *(const float4*)(Bg);
    float4 vb1 = *(const float4*)(Bg + 4);
    g_stage(sm, m_st, kh, va0, va1, vb0, vb1);
    __syncthreads();

    for (int kt = 0; kt < EE/16; kt++) {
        uint32_t* cur = sm + (kt & 1) * 4096;
        if (kt < EE/16 - 1) {
            const int off = (kt + 1) * 16;
            va0 = *(const float4*)(Ag + off);
            va1 = *(const float4*)(Ag + off + 4);
            vb0 = *(const float4*)(Bg + off);
            vb1 = *(const float4*)(Bg + off + 4);
        }
        g_tile(cur, wm, wn, lane, d);
        if (kt < EE/16 - 1)
            g_stage(sm + ((kt + 1) & 1) * 4096, m_st, kh, va0, va1, vb0, vb1);
        __syncthreads();
    }
}

// =====================================================================
// Kernel 1: fused QKV projections (bf16x3 mma).  grid (8,32,3), 256 thr.
// =====================================================================
__global__ __launch_bounds__(256, 1)
void qkv_mma(const float* __restrict__ qin, const float* __restrict__ kin,
             const float* __restrict__ vin,
             const float* __restrict__ wq, const float* __restrict__ bq,
             const float* __restrict__ wk, const float* __restrict__ bk,
             const float* __restrict__ wv, const float* __restrict__ bv)
{
    extern __shared__ uint32_t smw[];
    const int z = blockIdx.z;
    const float* A    = (z == 0) ? qin : (z == 1) ? kin : vin;
    const float* W    = (z == 0) ? wq  : (z == 1) ? wk  : wv;
    const float* bias = (z == 0) ? bq  : (z == 1) ? bk  : bv;
    float* Out        = (z == 0) ? g_q : (z == 1) ? g_k : g_v;

    const int m0 = blockIdx.y * 128;
    const int n0 = blockIdx.x * 128;
    const int tid = threadIdx.x;

    float d[4][4][4] = {};
    run_gemm(A + (size_t)m0 * EE, W + (size_t)n0 * EE, smw, tid, d);

    const int lane = tid & 31;
    const int w    = tid >> 5;
    const int wm   = w & 1;
    const int wn   = w >> 1;
    const int qrow = lane >> 2;
    const int qc   = (lane & 3) * 2;

    #pragma unroll
    for (int mt = 0; mt < 4; mt++) {
        const int gm0 = m0 + wm * 64 + mt * 16 + qrow;
        #pragma unroll
        for (int nt = 0; nt < 4; nt++) {
            const int gn = n0 + wn * 32 + nt * 8 + qc;
            const int h  = gn >> 6;
            const int dh = gn & 63;
            const float bx = bias[gn], by = bias[gn + 1];
            #pragma unroll
            for (int r = 0; r < 2; r++) {
                const int gm = gm0 + r * 8;
                const int b_ = gm >> 11;
                const int s_ = gm & (SS - 1);
                float2 o = make_float2(d[mt][nt][r * 2 + 0] + bx,
                                       d[mt][nt][r * 2 + 1] + by);
                *(float2*)(Out + (((size_t)(b_ * HH + h)) * SS + s_) * DH + dh) = o;
            }
        }
    }
}

// =====================================================================
// Kernel 3: output projection + residual (bf16x3 mma).
// =====================================================================
__global__ __launch_bounds__(256, 1)
void proj_mma(const float* __restrict__ query,
              const float* __restrict__ W, const float* __restrict__ bias)
{
    extern __shared__ uint32_t smw[];
    const int m0 = blockIdx.y * 128;
    const int n0 = blockIdx.x * 128;
    const int tid = threadIdx.x;

    float d[4][4][4] = {};
    run_gemm(g_att + (size_t)m0 * EE, W + (size_t)n0 * EE, smw, tid, d);

    const int lane = tid & 31;
    const int w    = tid >> 5;
    const int wm   = w & 1;
    const int wn   = w >> 1;
    const int qrow = lane >> 2;
    const int qc   = (lane & 3) * 2;

    #pragma unroll
    for (int mt = 0; mt < 4; mt++) {
        const int gm0 = m0 + wm * 64 + mt * 16 + qrow;
        #pragma unroll
        for (int nt = 0; nt < 4; nt++) {
            const int gn = n0 + wn * 32 + nt * 8 + qc;
            const float bx = bias[gn], by = bias[gn + 1];
            #pragma unroll
            for (int r = 0; r < 2; r++) {
                const int gm = gm0 + r * 8;
                const float* qp = query + (size_t)gm * EE + gn;
                float2 o = make_float2(d[mt][nt][r * 2 + 0] + bx + qp[0],
                                       d[mt][nt][r * 2 + 1] + by + qp[1]);
                *(float2*)(g_x + (size_t)gm * EE + gn) = o;
            }
        }
    }
}

// =====================================================================
// Kernel 2: causal flash attention, bf16x3 mma.
// grid (S/64, B*H), 128 threads (4 warps, 16 q-rows each).
// SMEM (36864B): Ksh[64][36] Ksl Vth[64][36] Vtl (words).
// K layout: word (kv, dhp) = kv*36 + dhp (bf16x2 along dh).
// Vt layout: word (dh, kvp) = dh*36 + kvp (bf16x2 along kv).
// =====================================================================
#define KROW 36
__global__ __launch_bounds__(128)
void attn_mma()
{
    extern __shared__ uint32_t smw[];
    uint32_t* Ksh = smw;
    uint32_t* Ksl = smw + 64*KROW;
    uint32_t* Vth = smw + 2*64*KROW;
    uint32_t* Vtl = smw + 3*64*KROW;

    const int bh = blockIdx.y;
    const int qt = blockIdx.x;
    const int tid = threadIdx.x;
    const int w    = tid >> 5;
    const int lane = tid & 31;
    const int qrow = lane >> 2;
    const int qk   = lane & 3;

    const float* Qg = g_q + (size_t)bh * SS * DH + (size_t)(qt*64 + w*16) * DH;
    const float* Kg = g_k + (size_t)bh * SS * DH;
    const float* Vg = g_v + (size_t)bh * SS * DH;

    // ---- Q fragments (register resident, hi+lo) ----
    uint32_t qh[16], ql[16];
    #pragma unroll
    for (int ks = 0; ks < 4; ks++) {
        float2 f0 = *(const float2*)(Qg + qrow*DH     + ks*16 + 2*qk);
        float2 f1 = *(const float2*)(Qg + (qrow+8)*DH + ks*16 + 2*qk);
        float2 f2 = *(const float2*)(Qg + qrow*DH     + ks*16 + 8 + 2*qk);
        float2 f3 = *(const float2*)(Qg + (qrow+8)*DH + ks*16 + 8 + 2*qk);
        bsplit2(f0.x, f0.y, qh[ks*4+0], ql[ks*4+0]);
        bsplit2(f1.x, f1.y, qh[ks*4+1], ql[ks*4+1]);
        bsplit2(f2.x, f2.y, qh[ks*4+2], ql[ks*4+2]);
        bsplit2(f3.x, f3.y, qh[ks*4+3], ql[ks*4+3]);
    }

    float ctx[8][4] = {};
    float mA = -1e30f, mB = -1e30f, lA = 0.f, lB = 0.f;
    const float CE = 0.125f * 1.44269504f;   // scale * log2(e)

    const int rowA = qt*64 + w*16 + qrow;    // global q index of rows A/B
    const int rowB = rowA + 8;

    for (int t = 0; t <= qt; t++) {
        __syncthreads();
        // ---- stage K tile: thread -> (kvr = tid>>1, dh half tid&1) ----
        {
            const int kvr = tid >> 1;
            const int dhb = (tid & 1) * 16;
            const float* kp = Kg + (size_t)(t*64 + kvr) * DH + dhb * 2;
            #pragma unroll
            for (int i = 0; i < 16; i++) {
                float2 f = *(const float2*)(kp + 2*i);
                uint32_t h, l;
                bsplit2(f.x, f.y, h, l);
                const int wd = kvr*KROW + dhb + i;
                Ksh[wd] = h; Ksl[wd] = l;
            }
        }
        // ---- stage V tile transposed: thread -> (dhr = tid>>1, kv half tid&1) ----
        {
            const int dhr = tid >> 1;
            const int kvb = (tid & 1) * 16;
            const float* vp = Vg + (size_t)(t*64) * DH + dhr;
            #pragma unroll
            for (int i = 0; i < 16; i++) {
                const int kvp = kvb + i;
                float v0 = vp[(size_t)(2*kvp) * DH];
                float v1 = vp[(size_t)(2*kvp+1) * DH];
                uint32_t h, l;
                bsplit2(v0, v1, h, l);
                const int wd = dhr*KROW + kvp;
                Vth[wd] = h; Vtl[wd] = l;
            }
        }
        __syncthreads();

        // ---- scores = Q K^T (bf16x3) ----
        float sc[8][4];
        #pragma unroll
        for (int nt = 0; nt < 8; nt++) {
            sc[nt][0] = sc[nt][1] = sc[nt][2] = sc[nt][3] = 0.f;
            const int kvr = nt*8 + qrow;
            #pragma unroll
            for (int ks = 0; ks < 4; ks++) {
                uint32_t b_h[2], b_l[2];
                const int wd = kvr*KROW + ks*8 + qk;
                b_h[0] = Ksh[wd]; b_h[1] = Ksh[wd + 4];
                b_l[0] = Ksl[wd]; b_l[1] = Ksl[wd + 4];
                mma_bf16(sc[nt], qh + 4*ks, b_h);
                mma_bf16(sc[nt], qh + 4*ks, b_l);
                mma_bf16(sc[nt], ql + 4*ks, b_h);
            }
        }

        // ---- causal mask (diagonal tile only) ----
        if (t == qt) {
            #pragma unroll
            for (int nt = 0; nt < 8; nt++) {
                const int col = t*64 + nt*8 + 2*qk;
                if (col     > rowA) sc[nt][0] = -1e30f;
                if (col + 1 > rowA) sc[nt][1] = -1e30f;
                if (col     > rowB) sc[nt][2] = -1e30f;
                if (col + 1 > rowB) sc[nt][3] = -1e30f;
            }
        }

        // ---- online softmax (rows A and B per lane) ----
        float mtA = -1e30f, mtB = -1e30f;
        #pragma unroll
        for (int nt = 0; nt < 8; nt++) {
            mtA = fmaxf(mtA, fmaxf(sc[nt][0], sc[nt][1]));
            mtB = fmaxf(mtB, fmaxf(sc[nt][2], sc[nt][3]));
        }
        mtA = fmaxf(mtA, __shfl_xor_sync(0xffffffffu, mtA, 1));
        mtA = fmaxf(mtA, __shfl_xor_sync(0xffffffffu, mtA, 2));
        mtB = fmaxf(mtB, __shfl_xor_sync(0xffffffffu, mtB, 1));
        mtB = fmaxf(mtB, __shfl_xor_sync(0xffffffffu, mtB, 2));
        const float mnA = fmaxf(mA, mtA);
        const float mnB = fmaxf(mB, mtB);
        const float alA = exp2f((mA - mnA) * CE);
        const float alB = exp2f((mB - mnB) * CE);
        mA = mnA; mB = mnB;

        float suA = 0.f, suB = 0.f;
        #pragma unroll
        for (int nt = 0; nt < 8; nt++) {
            sc[nt][0] = exp2f((sc[nt][0] - mnA) * CE);
            sc[nt][1] = exp2f((sc[nt][1] - mnA) * CE);
            sc[nt][2] = exp2f((sc[nt][2] - mnB) * CE);
            sc[nt][3] = exp2f((sc[nt][3] - mnB) * CE);
            suA += sc[nt][0] + sc[nt][1];
            suB += sc[nt][2] + sc[nt][3];
        }
        suA += __shfl_xor_sync(0xffffffffu, suA, 1);
        suA += __shfl_xor_sync(0xffffffffu, suA, 2);
        suB += __shfl_xor_sync(0xffffffffu, suB, 1);
        suB += __shfl_xor_sync(0xffffffffu, suB, 2);
        lA = lA * alA + suA;
        lB = lB * alB + suB;
        #pragma unroll
        for (int nt = 0; nt < 8; nt++) {
            ctx[nt][0] *= alA; ctx[nt][1] *= alA;
            ctx[nt][2] *= alB; ctx[nt][3] *= alB;
        }

        // ---- pack P into A-fragments (hi + lo) ----
        uint32_t ph[16], pl[16];
        #pragma unroll
        for (int ks = 0; ks < 4; ks++) {
            const int u0 = 2*ks, u1 = 2*ks + 1;
            bsplit2(sc[u0][0], sc[u0][1], ph[ks*4+0], pl[ks*4+0]);
            bsplit2(sc[u0][2], sc[u0][3], ph[ks*4+1], pl[ks*4+1]);
            bsplit2(sc[u1][0], sc[u1][1], ph[ks*4+2], pl[ks*4+2]);
            bsplit2(sc[u1][2], sc[u1][3], ph[ks*4+3], pl[ks*4+3]);
        }

        // ---- ctx += P V (bf16x3) ----
        #pragma unroll
        for (int nt = 0; nt < 8; nt++) {
            const int dhr = nt*8 + qrow;
            #pragma unroll
            for (int ks = 0; ks < 4; ks++) {
                uint32_t b_h[2], b_l[2];
                const int wd = dhr*KROW + ks*8 + qk;
                b_h[0] = Vth[wd]; b_h[1] = Vth[wd + 4];
                b_l[0] = Vtl[wd]; b_l[1] = Vtl[wd + 4];
                mma_bf16(ctx[nt], ph + 4*ks, b_h);
                mma_bf16(ctx[nt], ph + 4*ks, b_l);
                mma_bf16(ctx[nt], pl + 4*ks, b_h);
            }
        }
    }

    // ---- finalize & write to concat-heads layout ----
    const float ivA = 1.0f / lA;
    const float ivB = 1.0f / lB;
    const int b_ = bh >> 4;
    const int h_ = bh & 15;
    #pragma unroll
    for (int nt = 0; nt < 8; nt++) {
        const int dh = nt*8 + 2*qk;
        float2 oA = make_float2(ctx[nt][0]*ivA, ctx[nt][1]*ivA);
        float2 oB = make_float2(ctx[nt][2]*ivB, ctx[nt][3]*ivB);
        *(float2*)(g_att + ((size_t)(b_*SS + rowA))*EE + h_*64 + dh) = oA;
        *(float2*)(g_att + ((size_t)(b_*SS + rowB))*EE + h_*64 + dh) = oB;
    }
}

// =====================================================================
// Kernel 4: LayerNorm (unchanged).
// =====================================================================
__global__ __launch_bounds__(256)
void ln_kernel(const float* __restrict__ gamma, const float* __restrict__ beta,
               float* __restrict__ out)
{
    const int row = blockIdx.x;
    const float* x = g_x + (size_t)row * EE;
    const int tid = threadIdx.x;

    float4 v = *(const float4*)(x + tid * 4);
    float s = v.x + v.y + v.z + v.w;
    float q = v.x*v.x + v.y*v.y + v.z*v.z + v.w*v.w;
    #pragma unroll
    for (int off = 16; off; off >>= 1) {
        s += __shfl_xor_sync(0xffffffffu, s, off);
        q += __shfl_xor_sync(0xffffffffu, q, off);
    }
    __shared__ float ssum[8], ssq[8], stats[2];
    const int w = tid >> 5;
    if ((tid & 31) == 0) { ssum[w] = s; ssq[w] = q; }
    __syncthreads();
    if (tid < 32) {
        float s2 = (tid < 8) ? ssum[tid] : 0.f;
        float q2 = (tid < 8) ? ssq[tid]  : 0.f;
        #pragma unroll
        for (int off = 4; off; off >>= 1) {
            s2 += __shfl_xor_sync(0xffffffffu, s2, off);
            q2 += __shfl_xor_sync(0xffffffffu, q2, off);
        }
        if (tid == 0) {
            float mu = s2 * (1.0f / EE);
            float var = q2 * (1.0f / EE) - mu * mu;
            stats[0] = mu;
            stats[1] = rsqrtf(var + 1e-5f);
        }
    }
    __syncthreads();
    const float mu = stats[0];
    const float r  = stats[1];

    float4 gv = *(const float4*)(gamma + tid * 4);
    float4 bv = *(const float4*)(beta  + tid * 4);
    float4 o;
    o.x = (v.x - mu) * r * gv.x + bv.x;
    o.y = (v.y - mu) * r * gv.y + bv.y;
    o.z = (v.z - mu) * r * gv.z + bv.z;
    o.w = (v.w - mu) * r * gv.w + bv.w;
    *(float4*)(out + (size_t)row * EE + tid * 4) = o;
}

// =====================================================================
extern "C" void kernel_launch(void* const* d_in, const int* in_sizes, int n_in,
                              void* d_out, int out_size)
{
    (void)in_sizes; (void)n_in; (void)out_size;
    const float* query = (const float*)d_in[0];
    const float* key_i = (const float*)d_in[1];
    const float* value = (const float*)d_in[2];
    // d_in[3] = mask (causal; hard-coded in kernel)
    const float* Wq_w = (const float*)d_in[4];
    const float* Wq_b = (const float*)d_in[5];
    const float* Wk_w = (const float*)d_in[6];
    const float* Wk_b = (const float*)d_in[7];
    const float* Wv_w = (const float*)d_in[8];
    const float* Wv_b = (const float*)d_in[9];
    const float* out_w = (const float*)d_in[10];
    const float* out_b = (const float*)d_in[11];
    const float* ln_g = (const float*)d_in[12];
    const float* ln_b = (const float*)d_in[13];
    float* out = (float*)d_out;

    const int SMEM_GEMM = 2 * 4096 * 4;          // 32768 B
    const int SMEM_ATTN = 4 * 64 * KROW * 4;     // 36864 B

    // 1. QKV projections (bf16x3 mma)
    qkv_mma<<<dim3(EE/128, MM/128, 3), 256, SMEM_GEMM>>>(query, key_i, value,
                                                         Wq_w, Wq_b, Wk_w, Wk_b, Wv_w, Wv_b);

    // 2. causal flash attention (bf16x3 mma)
    attn_mma<<<dim3(SS/64, BB*HH), 128, SMEM_ATTN>>>();

    // 3. output projection + residual (bf16x3 mma)
    proj_mma<<<dim3(EE/128, MM/128), 256, SMEM_GEMM>>>(query, out_w, out_b);

    // 4. LayerNorm
    ln_kernel<<<MM, 256>>>(ln_g, ln_b, out);
}

// round 5
// speedup vs baseline: 2.9644x; 1.3877x over previous
#include <cuda_runtime.h>
#include <cuda_fp16.h>
#include <cstdint>
#include <math.h>

#define BB 2
#define SS 2048
#define EE 1024
#define HH 16
#define DH 64
#define MM (BB*SS)   // 4096

// ---------------- scratch (static device globals; no runtime alloc) ----------------
__device__ float g_q[BB*HH*SS*DH];   // [B,H,S,Dh]
__device__ float g_k[BB*HH*SS*DH];
__device__ float g_v[BB*HH*SS*DH];
__device__ float g_att[MM*EE];       // [B,S,E] concat heads
__device__ float g_x[MM*EE];         // residual + proj, pre-LN

// =====================================================================
// fp16 helpers
// =====================================================================
__device__ __forceinline__ void mma_fp16(float d[4], const uint32_t a[4], const uint32_t b[2]){
    asm volatile(
        "mma.sync.aligned.m16n8k16.row.col.f32.f16.f16.f32 "
        "{%0,%1,%2,%3}, {%4,%5,%6,%7}, {%8,%9}, {%0,%1,%2,%3};"
        : "+f"(d[0]), "+f"(d[1]), "+f"(d[2]), "+f"(d[3])
        : "r"(a[0]), "r"(a[1]), "r"(a[2]), "r"(a[3]),
          "r"(b[0]), "r"(b[1]));
}
__device__ __forceinline__ uint32_t hpack(float x, float y){
    __half2 h = __floats2half2_rn(x, y);
    return *(uint32_t*)&h;
}
__device__ __forceinline__ void sts_v4(uint32_t* p, uint32_t a, uint32_t b, uint32_t c, uint32_t d){
    uint4 v = make_uint4(a, b, c, d);
    *(uint4*)p = v;
}

// =====================================================================
// 128x128xK GEMM core, single-term fp16.  C = A[128,K] * B[128,K]^T
// 8 warps: wm = w&1 (64 rows), wn = w>>1 (32 cols). BK=16 per stage.
// Stage (8KB): Ah|Bh, each [128 rows][8 words] fp16x2 along k,
// word = row*8 + (kp ^ swz(row)),  swz = ((row&4)?4:0) ^ ((row&8)?2:0).
// Conflict-free for stores and all fragment load patterns. Double buffered.
// =====================================================================
__device__ __forceinline__ int gswz(int row){
    return ((row & 4) ? 4 : 0) ^ ((row & 8) ? 2 : 0);
}

__device__ __forceinline__ void g_stage(uint32_t* buf, int m, int kh,
                                        float4 a0, float4 a1, float4 b0, float4 b1)
{
    float av[8] = {a0.x,a0.y,a0.z,a0.w,a1.x,a1.y,a1.z,a1.w};
    float bv[8] = {b0.x,b0.y,b0.z,b0.w,b1.x,b1.y,b1.z,b1.w};
    const int sw = gswz(m);
    #pragma unroll
    for (int j = 0; j < 4; j++) {
        const int kp = kh*4 + j;
        const int wd = m*8 + (kp ^ sw);
        buf[wd]        = hpack(av[2*j], av[2*j+1]);
        buf[1024 + wd] = hpack(bv[2*j], bv[2*j+1]);
    }
}

__device__ __forceinline__ void g_tile(const uint32_t* buf, int wm, int wn,
                                       int lane, float d[4][4][4])
{
    const int qrow = lane >> 2;
    const int qk   = lane & 3;

    uint32_t a[4][4], b[4][2];
    #pragma unroll
    for (int mt = 0; mt < 4; mt++) {
        const int m  = wm*64 + mt*16 + qrow;      // bit3 = 0
        const int s0 = gswz(m);
        const int s1 = s0 ^ 2;                    // row m+8 flips bit3
        a[mt][0] = buf[m*8     + (qk       ^ s0)];
        a[mt][1] = buf[(m+8)*8 + (qk       ^ s1)];
        a[mt][2] = buf[m*8     + ((qk + 4) ^ s0)];
        a[mt][3] = buf[(m+8)*8 + ((qk + 4) ^ s1)];
    }
    #pragma unroll
    for (int nt = 0; nt < 4; nt++) {
        const int n  = wn*32 + nt*8 + qrow;
        const int sn = gswz(n);
        b[nt][0] = buf[1024 + n*8 + (qk       ^ sn)];
        b[nt][1] = buf[1024 + n*8 + ((qk + 4) ^ sn)];
    }
    #pragma unroll
    for (int mt = 0; mt < 4; mt++)
        #pragma unroll
        for (int nt = 0; nt < 4; nt++)
            mma_fp16(d[mt][nt], a[mt], b[nt]);
}

__device__ __forceinline__ void run_gemm(const float* __restrict__ A,
                                         const float* __restrict__ B,
                                         uint32_t* sm, int tid, float d[4][4][4])
{
    const int lane = tid & 31;
    const int w    = tid >> 5;
    const int wm   = w & 1;
    const int wn   = w >> 1;
    const int m_st = tid >> 1;           // 0..127
    const int kh   = tid & 1;            // which 8-float half of BK=16

    const float* Ag = A + (size_t)m_st * EE + kh * 8;
    const float* Bg = B + (size_t)m_st * EE + kh * 8;

    float4 va0 = *(const float4*)(Ag);
    float4 va1 = *(const float4*)(Ag + 4);
    float4 vb0 = *(const float4*)(Bg);
    float4 vb1 = *(const float4*)(Bg + 4);
    g_stage(sm, m_st, kh, va0, va1, vb0, vb1);
    __syncthreads();

    for (int kt = 0; kt < EE/16; kt++) {
        uint32_t* cur = sm + (kt & 1) * 2048;
        if (kt < EE/16 - 1) {
            const int off = (kt + 1) * 16;
            va0 = *(const float4*)(Ag + off);
            va1 = *(const float4*)(Ag + off + 4);
            vb0 = *(const float4*)(Bg + off);
            vb1 = *(const float4*)(Bg + off + 4);
        }
        g_tile(cur, wm, wn, lane, d);
        if (kt < EE/16 - 1)
            g_stage(sm + ((kt + 1) & 1) * 2048, m_st, kh, va0, va1, vb0, vb1);
        __syncthreads();
    }
}

// =====================================================================
// Kernel 1: fused QKV projections (fp16 mma).  grid (8,32,3), 256 thr.
// =====================================================================
__global__ __launch_bounds__(256, 1)
void qkv_mma(const float* __restrict__ qin, const float* __restrict__ kin,
             const float* __restrict__ vin,
             const float* __restrict__ wq, const float* __restrict__ bq,
             const float* __restrict__ wk, const float* __restrict__ bk,
             const float* __restrict__ wv, const float* __restrict__ bv)
{
    extern __shared__ uint32_t smw[];
    const int z = blockIdx.z;
    const float* A    = (z == 0) ? qin : (z == 1) ? kin : vin;
    const float* W    = (z == 0) ? wq  : (z == 1) ? wk  : wv;
    const float* bias = (z == 0) ? bq  : (z == 1) ? bk  : bv;
    float* Out        = (z == 0) ? g_q : (z == 1) ? g_k : g_v;

    const int m0 = blockIdx.y * 128;
    const int n0 = blockIdx.x * 128;
    const int tid = threadIdx.x;

    float d[4][4][4] = {};
    run_gemm(A + (size_t)m0 * EE, W + (size_t)n0 * EE, smw, tid, d);

    const int lane = tid & 31;
    const int w    = tid >> 5;
    const int wm   = w & 1;
    const int wn   = w >> 1;
    const int qrow = lane >> 2;
    const int qc   = (lane & 3) * 2;

    #pragma unroll
    for (int mt = 0; mt < 4; mt++) {
        const int gm0 = m0 + wm * 64 + mt * 16 + qrow;
        #pragma unroll
        for (int nt = 0; nt < 4; nt++) {
            const int gn = n0 + wn * 32 + nt * 8 + qc;
            const int h  = gn >> 6;
            const int dh = gn & 63;
            const float bx = bias[gn], by = bias[gn + 1];
            #pragma unroll
            for (int r = 0; r < 2; r++) {
                const int gm = gm0 + r * 8;
                const int b_ = gm >> 11;
                const int s_ = gm & (SS - 1);
                float2 o = make_float2(d[mt][nt][r * 2 + 0] + bx,
                                       d[mt][nt][r * 2 + 1] + by);
                *(float2*)(Out + (((size_t)(b_ * HH + h)) * SS + s_) * DH + dh) = o;
            }
        }
    }
}

// =====================================================================
// Kernel 3: output projection + residual (fp16 mma).
// =====================================================================
__global__ __launch_bounds__(256, 1)
void proj_mma(const float* __restrict__ query,
              const float* __restrict__ W, const float* __restrict__ bias)
{
    extern __shared__ uint32_t smw[];
    const int m0 = blockIdx.y * 128;
    const int n0 = blockIdx.x * 128;
    const int tid = threadIdx.x;

    float d[4][4][4] = {};
    run_gemm(g_att + (size_t)m0 * EE, W + (size_t)n0 * EE, smw, tid, d);

    const int lane = tid & 31;
    const int w    = tid >> 5;
    const int wm   = w & 1;
    const int wn   = w >> 1;
    const int qrow = lane >> 2;
    const int qc   = (lane & 3) * 2;

    #pragma unroll
    for (int mt = 0; mt < 4; mt++) {
        const int gm0 = m0 + wm * 64 + mt * 16 + qrow;
        #pragma unroll
        for (int nt = 0; nt < 4; nt++) {
            const int gn = n0 + wn * 32 + nt * 8 + qc;
            const float bx = bias[gn], by = bias[gn + 1];
            #pragma unroll
            for (int r = 0; r < 2; r++) {
                const int gm = gm0 + r * 8;
                const float* qp = query + (size_t)gm * EE + gn;
                float2 o = make_float2(d[mt][nt][r * 2 + 0] + bx + qp[0],
                                       d[mt][nt][r * 2 + 1] + by + qp[1]);
                *(float2*)(g_x + (size_t)gm * EE + gn) = o;
            }
        }
    }
}

// =====================================================================
// Kernel 2: causal flash attention, single-term fp16 mma.
// grid (S/64, B*H), 128 threads (4 warps, 16 q-rows each).
// SMEM (18KB): Ks[64][36] (fp16x2 along dh), Vt[64][36] (fp16x2 along kv).
// =====================================================================
#define KROW 36
__global__ __launch_bounds__(128)
void attn_mma()
{
    extern __shared__ uint32_t smw[];
    uint32_t* Ks = smw;
    uint32_t* Vt = smw + 64*KROW;

    const int bh = blockIdx.y;
    const int qt = blockIdx.x;
    const int tid = threadIdx.x;
    const int w    = tid >> 5;
    const int lane = tid & 31;
    const int qrow = lane >> 2;
    const int qk   = lane & 3;

    const float* Qg = g_q + (size_t)bh * SS * DH + (size_t)(qt*64 + w*16) * DH;
    const float* Kg = g_k + (size_t)bh * SS * DH;
    const float* Vg = g_v + (size_t)bh * SS * DH;

    // ---- Q fragments (register resident) ----
    uint32_t qh[16];
    #pragma unroll
    for (int ks = 0; ks < 4; ks++) {
        float2 f0 = *(const float2*)(Qg + qrow*DH     + ks*16 + 2*qk);
        float2 f1 = *(const float2*)(Qg + (qrow+8)*DH + ks*16 + 2*qk);
        float2 f2 = *(const float2*)(Qg + qrow*DH     + ks*16 + 8 + 2*qk);
        float2 f3 = *(const float2*)(Qg + (qrow+8)*DH + ks*16 + 8 + 2*qk);
        qh[ks*4+0] = hpack(f0.x, f0.y);
        qh[ks*4+1] = hpack(f1.x, f1.y);
        qh[ks*4+2] = hpack(f2.x, f2.y);
        qh[ks*4+3] = hpack(f3.x, f3.y);
    }

    float ctx[8][4] = {};
    float mA = -1e30f, mB = -1e30f, lA = 0.f, lB = 0.f;
    const float CE = 0.125f * 1.44269504f;   // scale * log2(e)

    const int rowA = qt*64 + w*16 + qrow;    // global q index of rows A/B
    const int rowB = rowA + 8;

    for (int t = 0; t <= qt; t++) {
        __syncthreads();
        // ---- stage K tile: thread -> (kvr = tid>>1, dh-word half tid&1) ----
        {
            const int kvr = tid >> 1;
            const int dww = (tid & 1) * 16;                 // word offset 0 or 16
            const float* kp = Kg + (size_t)(t*64 + kvr) * DH + dww * 2;
            uint32_t wv_[16];
            #pragma unroll
            for (int i = 0; i < 8; i++) {
                float4 f = *(const float4*)(kp + 4*i);
                wv_[2*i]   = hpack(f.x, f.y);
                wv_[2*i+1] = hpack(f.z, f.w);
            }
            uint32_t* dst = Ks + kvr*KROW + dww;
            sts_v4(dst,      wv_[0],  wv_[1],  wv_[2],  wv_[3]);
            sts_v4(dst + 4,  wv_[4],  wv_[5],  wv_[6],  wv_[7]);
            sts_v4(dst + 8,  wv_[8],  wv_[9],  wv_[10], wv_[11]);
            sts_v4(dst + 12, wv_[12], wv_[13], wv_[14], wv_[15]);
        }
        // ---- stage V tile transposed, coalesced:
        //      thread -> kvp j = tid&31, dh block dblk = tid>>5 (16 dh) ----
        {
            const int j    = tid & 31;
            const int dblk = tid >> 5;
            const float* v0 = Vg + (size_t)(t*64 + 2*j)     * DH + dblk*16;
            const float* v1 = Vg + (size_t)(t*64 + 2*j + 1) * DH + dblk*16;
            float4 r0[4], r1[4];
            #pragma unroll
            for (int u = 0; u < 4; u++) {
                r0[u] = *(const float4*)(v0 + 4*u);
                r1[u] = *(const float4*)(v1 + 4*u);
            }
            const float* p0 = (const float*)r0;
            const float* p1 = (const float*)r1;
            #pragma unroll
            for (int i = 0; i < 16; i++)
                Vt[(dblk*16 + i)*KROW + j] = hpack(p0[i], p1[i]);
        }
        __syncthreads();

        // ---- scores = Q K^T ----
        float sc[8][4];
        #pragma unroll
        for (int nt = 0; nt < 8; nt++) {
            sc[nt][0] = sc[nt][1] = sc[nt][2] = sc[nt][3] = 0.f;
            const int kvr = nt*8 + qrow;
            #pragma unroll
            for (int ks = 0; ks < 4; ks++) {
                uint32_t b_[2];
                const int wd = kvr*KROW + ks*8 + qk;
                b_[0] = Ks[wd]; b_[1] = Ks[wd + 4];
                mma_fp16(sc[nt], qh + 4*ks, b_);
            }
        }

        // ---- causal mask (diagonal tile only) ----
        if (t == qt) {
            #pragma unroll
            for (int nt = 0; nt < 8; nt++) {
                const int col = t*64 + nt*8 + 2*qk;
                if (col     > rowA) sc[nt][0] = -1e30f;
                if (col + 1 > rowA) sc[nt][1] = -1e30f;
                if (col     > rowB) sc[nt][2] = -1e30f;
                if (col + 1 > rowB) sc[nt][3] = -1e30f;
            }
        }

        // ---- online softmax (rows A and B per lane) ----
        float mtA = -1e30f, mtB = -1e30f;
        #pragma unroll
        for (int nt = 0; nt < 8; nt++) {
            mtA = fmaxf(mtA, fmaxf(sc[nt][0], sc[nt][1]));
            mtB = fmaxf(mtB, fmaxf(sc[nt][2], sc[nt][3]));
        }
        mtA = fmaxf(mtA, __shfl_xor_sync(0xffffffffu, mtA, 1));
        mtA = fmaxf(mtA, __shfl_xor_sync(0xffffffffu, mtA, 2));
        mtB = fmaxf(mtB, __shfl_xor_sync(0xffffffffu, mtB, 1));
        mtB = fmaxf(mtB, __shfl_xor_sync(0xffffffffu, mtB, 2));
        const float mnA = fmaxf(mA, mtA);
        const float mnB = fmaxf(mB, mtB);
        const float alA = exp2f((mA - mnA) * CE);
        const float alB = exp2f((mB - mnB) * CE);
        mA = mnA; mB = mnB;

        float suA = 0.f, suB = 0.f;
        #pragma unroll
        for (int nt = 0; nt < 8; nt++) {
            sc[nt][0] = exp2f((sc[nt][0] - mnA) * CE);
            sc[nt][1] = exp2f((sc[nt][1] - mnA) * CE);
            sc[nt][2] = exp2f((sc[nt][2] - mnB) * CE);
            sc[nt][3] = exp2f((sc[nt][3] - mnB) * CE);
            suA += sc[nt][0] + sc[nt][1];
            suB += sc[nt][2] + sc[nt][3];
        }
        suA += __shfl_xor_sync(0xffffffffu, suA, 1);
        suA += __shfl_xor_sync(0xffffffffu, suA, 2);
        suB += __shfl_xor_sync(0xffffffffu, suB, 1);
        suB += __shfl_xor_sync(0xffffffffu, suB, 2);
        lA = lA * alA + suA;
        lB = lB * alB + suB;
        #pragma unroll
        for (int nt = 0; nt < 8; nt++) {
            ctx[nt][0] *= alA; ctx[nt][1] *= alA;
            ctx[nt][2] *= alB; ctx[nt][3] *= alB;
        }

        // ---- pack P into A-fragments ----
        uint32_t ph[16];
        #pragma unroll
        for (int ks = 0; ks < 4; ks++) {
            const int u0 = 2*ks, u1 = 2*ks + 1;
            ph[ks*4+0] = hpack(sc[u0][0], sc[u0][1]);
            ph[ks*4+1] = hpack(sc[u0][2], sc[u0][3]);
            ph[ks*4+2] = hpack(sc[u1][0], sc[u1][1]);
            ph[ks*4+3] = hpack(sc[u1][2], sc[u1][3]);
        }

        // ---- ctx += P V ----
        #pragma unroll
        for (int nt = 0; nt < 8; nt++) {
            const int dhr = nt*8 + qrow;
            #pragma unroll
            for (int ks = 0; ks < 4; ks++) {
                uint32_t b_[2];
                const int wd = dhr*KROW + ks*8 + qk;
                b_[0] = Vt[wd]; b_[1] = Vt[wd + 4];
                mma_fp16(ctx[nt], ph + 4*ks, b_);
            }
        }
    }

    // ---- finalize & write to concat-heads layout ----
    const float ivA = 1.0f / lA;
    const float ivB = 1.0f / lB;
    const int b_ = bh >> 4;
    const int h_ = bh & 15;
    #pragma unroll
    for (int nt = 0; nt < 8; nt++) {
        const int dh = nt*8 + 2*qk;
        float2 oA = make_float2(ctx[nt][0]*ivA, ctx[nt][1]*ivA);
        float2 oB = make_float2(ctx[nt][2]*ivB, ctx[nt][3]*ivB);
        *(float2*)(g_att + ((size_t)(b_*SS + rowA))*EE + h_*64 + dh) = oA;
        *(float2*)(g_att + ((size_t)(b_*SS + rowB))*EE + h_*64 + dh) = oB;
    }
}

// =====================================================================
// Kernel 4: LayerNorm (unchanged).
// =====================================================================
__global__ __launch_bounds__(256)
void ln_kernel(const float* __restrict__ gamma, const float* __restrict__ beta,
               float* __restrict__ out)
{
    const int row = blockIdx.x;
    const float* x = g_x + (size_t)row * EE;
    const int tid = threadIdx.x;

    float4 v = *(const float4*)(x + tid * 4);
    float s = v.x + v.y + v.z + v.w;
    float q = v.x*v.x + v.y*v.y + v.z*v.z + v.w*v.w;
    #pragma unroll
    for (int off = 16; off; off >>= 1) {
        s += __shfl_xor_sync(0xffffffffu, s, off);
        q += __shfl_xor_sync(0xffffffffu, q, off);
    }
    __shared__ float ssum[8], ssq[8], stats[2];
    const int w = tid >> 5;
    if ((tid & 31) == 0) { ssum[w] = s; ssq[w] = q; }
    __syncthreads();
    if (tid < 32) {
        float s2 = (tid < 8) ? ssum[tid] : 0.f;
        float q2 = (tid < 8) ? ssq[tid]  : 0.f;
        #pragma unroll
        for (int off = 4; off; off >>= 1) {
            s2 += __shfl_xor_sync(0xffffffffu, s2, off);
            q2 += __shfl_xor_sync(0xffffffffu, q2, off);
        }
        if (tid == 0) {
            float mu = s2 * (1.0f / EE);
            float var = q2 * (1.0f / EE) - mu * mu;
            stats[0] = mu;
            stats[1] = rsqrtf(var + 1e-5f);
        }
    }
    __syncthreads();
    const float mu = stats[0];
    const float r  = stats[1];

    float4 gv = *(const float4*)(gamma + tid * 4);
    float4 bv = *(const float4*)(beta  + tid * 4);
    float4 o;
    o.x = (v.x - mu) * r * gv.x + bv.x;
    o.y = (v.y - mu) * r * gv.y + bv.y;
    o.z = (v.z - mu) * r * gv.z + bv.z;
    o.w = (v.w - mu) * r * gv.w + bv.w;
    *(float4*)(out + (size_t)row * EE + tid * 4) = o;
}

// =====================================================================
extern "C" void kernel_launch(void* const* d_in, const int* in_sizes, int n_in,
                              void* d_out, int out_size)
{
    (void)in_sizes; (void)n_in; (void)out_size;
    const float* query = (const float*)d_in[0];
    const float* key_i = (const float*)d_in[1];
    const float* value = (const float*)d_in[2];
    // d_in[3] = mask (causal; hard-coded in kernel)
    const float* Wq_w = (const float*)d_in[4];
    const float* Wq_b = (const float*)d_in[5];
    const float* Wk_w = (const float*)d_in[6];
    const float* Wk_b = (const float*)d_in[7];
    const float* Wv_w = (const float*)d_in[8];
    const float* Wv_b = (const float*)d_in[9];
    const float* out_w = (const float*)d_in[10];
    const float* out_b = (const float*)d_in[11];
    const float* ln_g = (const float*)d_in[12];
    const float* ln_b = (const float*)d_in[13];
    float* out = (float*)d_out;

    const int SMEM_GEMM = 2 * 2048 * 4;          // 16384 B
    const int SMEM_ATTN = 2 * 64 * KROW * 4;     // 18432 B

    // 1. QKV projections (fp16 mma)
    qkv_mma<<<dim3(EE/128, MM/128, 3), 256, SMEM_GEMM>>>(query, key_i, value,
                                                         Wq_w, Wq_b, Wk_w, Wk_b, Wv_w, Wv_b);

    // 2. causal flash attention (fp16 mma)
    attn_mma<<<dim3(SS/64, BB*HH), 128, SMEM_ATTN>>>();

    // 3. output projection + residual (fp16 mma)
    proj_mma<<<dim3(EE/128, MM/128), 256, SMEM_GEMM>>>(query, out_w, out_b);

    // 4. LayerNorm
    ln_kernel<<<MM, 256>>>(ln_g, ln_b, out);
}

// round 6
// speedup vs baseline: 5.1696x; 1.7439x over previous
#include <cuda_runtime.h>
#include <cuda_fp16.h>
#include <cstdint>
#include <math.h>

#define BB 2
#define SS 2048
#define EE 1024
#define HH 16
#define DH 64
#define MM (BB*SS)   // 4096

// ---------------- scratch (static device globals; no runtime alloc) ----------------
__device__ __half g_inq[MM*EE], g_ink[MM*EE], g_inv[MM*EE];       // fp16 inputs
__device__ __half g_wq[EE*EE], g_wk[EE*EE], g_wv[EE*EE], g_wo[EE*EE]; // fp16 weights
__device__ __half g_qh[BB*HH*SS*DH], g_kh[BB*HH*SS*DH], g_vh[BB*HH*SS*DH]; // [B,H,S,Dh]
__device__ __half g_atth[MM*EE];   // concat heads, fp16
__device__ float  g_x[MM*EE];      // residual + proj, pre-LN (fp32)

// =====================================================================
// helpers
// =====================================================================
__device__ __forceinline__ uint32_t smem_u32(const void* p){
    uint32_t a;
    asm("{ .reg .u64 t; cvta.to.shared.u64 t, %1; cvt.u32.u64 %0, t; }" : "=r"(a) : "l"(p));
    return a;
}
__device__ __forceinline__ void mma_fp16(float d[4], const uint32_t a[4], const uint32_t b[2]){
    asm volatile(
        "mma.sync.aligned.m16n8k16.row.col.f32.f16.f16.f32 "
        "{%0,%1,%2,%3}, {%4,%5,%6,%7}, {%8,%9}, {%0,%1,%2,%3};"
        : "+f"(d[0]), "+f"(d[1]), "+f"(d[2]), "+f"(d[3])
        : "r"(a[0]), "r"(a[1]), "r"(a[2]), "r"(a[3]),
          "r"(b[0]), "r"(b[1]));
}
__device__ __forceinline__ uint32_t hpack(float x, float y){
    __half2 h = __floats2half2_rn(x, y);
    return *(uint32_t*)&h;
}
__device__ __forceinline__ void cp16(uint32_t dst, const void* src){
    asm volatile("cp.async.cg.shared.global [%0], [%1], 16;" :: "r"(dst), "l"(src));
}
#define CP_COMMIT() asm volatile("cp.async.commit_group;" ::: "memory")
#define CP_WAIT(n)  asm volatile("cp.async.wait_group %0;" :: "n"(n) : "memory")
__device__ __forceinline__ void ldm_x4(uint32_t a[4], uint32_t addr){
    asm volatile("ldmatrix.sync.aligned.m8n8.x4.shared.b16 {%0,%1,%2,%3}, [%4];"
        : "=r"(a[0]), "=r"(a[1]), "=r"(a[2]), "=r"(a[3]) : "r"(addr));
}
__device__ __forceinline__ void ldm_x2(uint32_t b[2], uint32_t addr){
    asm volatile("ldmatrix.sync.aligned.m8n8.x2.shared.b16 {%0,%1}, [%2];"
        : "=r"(b[0]), "=r"(b[1]) : "r"(addr));
}

// =====================================================================
// Kernel 0: fp32 -> fp16 conversion of inputs + weights (once).
// =====================================================================
__global__ __launch_bounds__(256)
void cvt_all(const float* __restrict__ q, const float* __restrict__ k,
             const float* __restrict__ v, const float* __restrict__ wq,
             const float* __restrict__ wk, const float* __restrict__ wv,
             const float* __restrict__ wo)
{
    const int i  = blockIdx.x * 256 + threadIdx.x;   // float4 index
    const int S1 = MM * EE / 4;
    const int S2 = EE * EE / 4;
    const float* src; __half* dst; int idx;
    if (i < S1)            { src = q;  dst = g_inq; idx = i; }
    else if (i < 2*S1)     { src = k;  dst = g_ink; idx = i - S1; }
    else if (i < 3*S1)     { src = v;  dst = g_inv; idx = i - 2*S1; }
    else {
        const int j = i - 3*S1;
        if (j < S2)        { src = wq; dst = g_wq; idx = j; }
        else if (j < 2*S2) { src = wk; dst = g_wk; idx = j - S2; }
        else if (j < 3*S2) { src = wv; dst = g_wv; idx = j - 2*S2; }
        else               { src = wo; dst = g_wo; idx = j - 3*S2; }
    }
    float4 f = ((const float4*)src)[idx];
    uint2 u;
    u.x = hpack(f.x, f.y);
    u.y = hpack(f.z, f.w);
    ((uint2*)dst)[idx] = u;
}

// =====================================================================
// fp16 GEMM core: C[128,128] = A[128,K] * B[128,K]^T, 4 warps, 64x64/warp.
// cp.async 3-stage (8KB/stage: A[128][8w] + B[128][8w], chunk-swizzled),
// ldmatrix fragment loads.
// =====================================================================
__device__ __forceinline__ void g_issue(uint32_t a_dst, uint32_t b_dst, int swc_,
                                        const __half* Ag, const __half* Bg, int kt)
{
    const __half* as = Ag + kt * 16;
    const __half* bs = Bg + kt * 16;
    cp16(a_dst + (0 ^ swc_) * 16, as);
    cp16(a_dst + (1 ^ swc_) * 16, as + 8);
    cp16(b_dst + (0 ^ swc_) * 16, bs);
    cp16(b_dst + (1 ^ swc_) * 16, bs + 8);
}

__device__ __forceinline__ void run_gemm_h(const __half* __restrict__ A,
                                           const __half* __restrict__ B,
                                           uint32_t smb, int tid, float d[4][8][4])
{
    const int lane = tid & 31;
    const int w  = tid >> 5;
    const int wm = w & 1;
    const int wn = w >> 1;

    const __half* Ag = A + (size_t)tid * EE;   // staging row = tid (0..127)
    const __half* Bg = B + (size_t)tid * EE;
    const int swc_ = (tid & 4) >> 2;
    const uint32_t a_dst = smb + tid * 32;
    const uint32_t b_dst = smb + 4096 + tid * 32;

    // prologue: stages 0,1
    g_issue(a_dst,          b_dst,          swc_, Ag, Bg, 0); CP_COMMIT();
    g_issue(a_dst + 8192,   b_dst + 8192,   swc_, Ag, Bg, 1); CP_COMMIT();

    // ldmatrix lane-address bases
    const int l15 = lane & 15;
    const int ach = ((lane >> 4) ^ ((l15 & 4) >> 2));
    const uint32_t a_addr0 = smb + (uint32_t)(wm*64 + l15) * 32 + ach * 16;
    const int l7 = lane & 7;
    const int bch = (((lane >> 3) & 1) ^ ((l7 & 4) >> 2));
    const uint32_t b_addr0 = smb + 4096 + (uint32_t)(wn*64 + l7) * 32 + bch * 16;

    for (int kt = 0; kt < EE/16; kt++) {
        CP_WAIT(1);
        __syncthreads();
        if (kt + 2 < EE/16) {
            const uint32_t off = (uint32_t)((kt + 2) % 3) * 8192;
            g_issue(a_dst + off, b_dst + off, swc_, Ag, Bg, kt + 2);
        }
        CP_COMMIT();
        const uint32_t so = (uint32_t)(kt % 3) * 8192;
        uint32_t a[4][4], b2[8][2];
        #pragma unroll
        for (int mt = 0; mt < 4; mt++) ldm_x4(a[mt], a_addr0 + so + mt * 512);
        #pragma unroll
        for (int nt = 0; nt < 8; nt++) ldm_x2(b2[nt], b_addr0 + so + nt * 256);
        #pragma unroll
        for (int mt = 0; mt < 4; mt++)
            #pragma unroll
            for (int nt = 0; nt < 8; nt++)
                mma_fp16(d[mt][nt], a[mt], b2[nt]);
    }
}

// =====================================================================
// Kernel 1: fused QKV projections.  grid (8, 32, 3), 128 threads.
// Writes g_qh/g_kh/g_vh (fp16, [B,H,S,Dh]).
// =====================================================================
__global__ __launch_bounds__(128)
void qkv_mma(const float* __restrict__ bq, const float* __restrict__ bk,
             const float* __restrict__ bv)
{
    extern __shared__ uint32_t smw[];
    const int z = blockIdx.z;
    const __half* A    = (z == 0) ? g_inq : (z == 1) ? g_ink : g_inv;
    const __half* W    = (z == 0) ? g_wq  : (z == 1) ? g_wk  : g_wv;
    const float* bias  = (z == 0) ? bq    : (z == 1) ? bk    : bv;
    __half* Out        = (z == 0) ? g_qh  : (z == 1) ? g_kh  : g_vh;

    const int m0 = blockIdx.y * 128;
    const int n0 = blockIdx.x * 128;
    const int tid = threadIdx.x;

    float d[4][8][4] = {};
    run_gemm_h(A + (size_t)m0 * EE, W + (size_t)n0 * EE, smem_u32(smw), tid, d);

    const int lane = tid & 31;
    const int w  = tid >> 5;
    const int wm = w & 1;
    const int wn = w >> 1;
    const int qrow = lane >> 2;
    const int qc   = (lane & 3) * 2;

    #pragma unroll
    for (int mt = 0; mt < 4; mt++) {
        const int gm0 = m0 + wm * 64 + mt * 16 + qrow;
        #pragma unroll
        for (int nt = 0; nt < 8; nt++) {
            const int gn = n0 + wn * 64 + nt * 8 + qc;
            const int h  = gn >> 6;
            const int dh = gn & 63;
            const float bx = bias[gn], by = bias[gn + 1];
            #pragma unroll
            for (int r = 0; r < 2; r++) {
                const int gm = gm0 + r * 8;
                const int b_ = gm >> 11;
                const int s_ = gm & (SS - 1);
                uint32_t o = hpack(d[mt][nt][r*2+0] + bx, d[mt][nt][r*2+1] + by);
                *(uint32_t*)(Out + (((size_t)(b_*HH + h))*SS + s_)*DH + dh) = o;
            }
        }
    }
}

// =====================================================================
// Kernel 3: output projection + residual.  A = g_atth (fp16), B = g_wo.
// =====================================================================
__global__ __launch_bounds__(128)
void proj_mma(const float* __restrict__ query, const float* __restrict__ bias)
{
    extern __shared__ uint32_t smw[];
    const int m0 = blockIdx.y * 128;
    const int n0 = blockIdx.x * 128;
    const int tid = threadIdx.x;

    float d[4][8][4] = {};
    run_gemm_h(g_atth + (size_t)m0 * EE, g_wo + (size_t)n0 * EE, smem_u32(smw), tid, d);

    const int lane = tid & 31;
    const int w  = tid >> 5;
    const int wm = w & 1;
    const int wn = w >> 1;
    const int qrow = lane >> 2;
    const int qc   = (lane & 3) * 2;

    #pragma unroll
    for (int mt = 0; mt < 4; mt++) {
        const int gm0 = m0 + wm * 64 + mt * 16 + qrow;
        #pragma unroll
        for (int nt = 0; nt < 8; nt++) {
            const int gn = n0 + wn * 64 + nt * 8 + qc;
            const float bx = bias[gn], by = bias[gn + 1];
            #pragma unroll
            for (int r = 0; r < 2; r++) {
                const int gm = gm0 + r * 8;
                const float* qp = query + (size_t)gm * EE + gn;
                float2 o = make_float2(d[mt][nt][r*2+0] + bx + qp[0],
                                       d[mt][nt][r*2+1] + by + qp[1]);
                *(float2*)(g_x + (size_t)gm * EE + gn) = o;
            }
        }
    }
}

// =====================================================================
// Kernel 2: causal flash attention, fp16 mma, fp16 storage.
// grid (S/64, B*H), 128 threads (4 warps x 16 q-rows).
// SMEM (18KB): Ks[64][36] (fp16x2 along dh), Vt[64][36] (fp16x2 along kv).
// =====================================================================
#define KROW 36
__global__ __launch_bounds__(128)
void attn_mma()
{
    extern __shared__ uint32_t smw[];
    uint32_t* Ks = smw;
    uint32_t* Vt = smw + 64*KROW;
    const uint32_t KsAddr = smem_u32(smw);

    const int bh = blockIdx.y;
    const int qt = gridDim.x - 1 - blockIdx.x;   // big tiles first
    const int tid = threadIdx.x;
    const int w    = tid >> 5;
    const int lane = tid & 31;
    const int qrow = lane >> 2;
    const int qk   = lane & 3;

    const __half* Qg = g_qh + (size_t)bh * SS * DH + (size_t)(qt*64 + w*16) * DH;
    const __half* Kg = g_kh + (size_t)bh * SS * DH;
    const __half* Vg = g_vh + (size_t)bh * SS * DH;

    // ---- Q fragments (register resident, fp16 direct) ----
    uint32_t qh[16];
    #pragma unroll
    for (int ks = 0; ks < 4; ks++) {
        qh[ks*4+0] = *(const uint32_t*)(Qg + qrow*DH     + ks*16 + 2*qk);
        qh[ks*4+1] = *(const uint32_t*)(Qg + (qrow+8)*DH + ks*16 + 2*qk);
        qh[ks*4+2] = *(const uint32_t*)(Qg + qrow*DH     + ks*16 + 8 + 2*qk);
        qh[ks*4+3] = *(const uint32_t*)(Qg + (qrow+8)*DH + ks*16 + 8 + 2*qk);
    }

    float ctx[8][4] = {};
    float mA = -1e30f, mB = -1e30f, lA = 0.f, lB = 0.f;
    const float CE = 0.125f * 1.44269504f;   // scale * log2(e)

    const int rowA = qt*64 + w*16 + qrow;
    const int rowB = rowA + 8;

    for (int t = 0; t <= qt; t++) {
        __syncthreads();
        // ---- stage K tile via cp.async (pure fp16 copy) ----
        #pragma unroll
        for (int i = 0; i < 4; i++) {
            const int ci  = tid*4 + i;
            const int row = ci >> 3;
            const int c   = ci & 7;
            cp16(KsAddr + (uint32_t)(row*KROW + c*4) * 4,
                 Kg + (size_t)(t*64 + row) * DH + c*8);
        }
        CP_COMMIT();
        // ---- stage V transposed via byte_perm ----
        {
            const int j    = tid & 31;
            const int dblk = tid >> 5;
            const __half* v0 = Vg + (size_t)(t*64 + 2*j) * DH + dblk*16;
            const __half* v1 = v0 + DH;
            uint4 a0 = *(const uint4*)(v0);
            uint4 a1 = *(const uint4*)(v0 + 8);
            uint4 c0 = *(const uint4*)(v1);
            uint4 c1 = *(const uint4*)(v1 + 8);
            uint32_t w0[8] = {a0.x,a0.y,a0.z,a0.w, a1.x,a1.y,a1.z,a1.w};
            uint32_t w1[8] = {c0.x,c0.y,c0.z,c0.w, c1.x,c1.y,c1.z,c1.w};
            #pragma unroll
            for (int i = 0; i < 8; i++) {
                Vt[(dblk*16 + 2*i    )*KROW + j] = __byte_perm(w0[i], w1[i], 0x5410);
                Vt[(dblk*16 + 2*i + 1)*KROW + j] = __byte_perm(w0[i], w1[i], 0x7632);
            }
        }
        CP_WAIT(0);
        __syncthreads();

        // ---- scores = Q K^T ----
        float sc[8][4];
        #pragma unroll
        for (int nt = 0; nt < 8; nt++) {
            sc[nt][0] = sc[nt][1] = sc[nt][2] = sc[nt][3] = 0.f;
            const int kvr = nt*8 + qrow;
            #pragma unroll
            for (int ks = 0; ks < 4; ks++) {
                uint32_t b_[2];
                const int wd = kvr*KROW + ks*8 + qk;
                b_[0] = Ks[wd]; b_[1] = Ks[wd + 4];
                mma_fp16(sc[nt], qh + 4*ks, b_);
            }
        }

        // ---- causal mask (diagonal tile only) ----
        if (t == qt) {
            #pragma unroll
            for (int nt = 0; nt < 8; nt++) {
                const int col = t*64 + nt*8 + 2*qk;
                if (col     > rowA) sc[nt][0] = -1e30f;
                if (col + 1 > rowA) sc[nt][1] = -1e30f;
                if (col     > rowB) sc[nt][2] = -1e30f;
                if (col + 1 > rowB) sc[nt][3] = -1e30f;
            }
        }

        // ---- online softmax ----
        float mtA = -1e30f, mtB = -1e30f;
        #pragma unroll
        for (int nt = 0; nt < 8; nt++) {
            mtA = fmaxf(mtA, fmaxf(sc[nt][0], sc[nt][1]));
            mtB = fmaxf(mtB, fmaxf(sc[nt][2], sc[nt][3]));
        }
        mtA = fmaxf(mtA, __shfl_xor_sync(0xffffffffu, mtA, 1));
        mtA = fmaxf(mtA, __shfl_xor_sync(0xffffffffu, mtA, 2));
        mtB = fmaxf(mtB, __shfl_xor_sync(0xffffffffu, mtB, 1));
        mtB = fmaxf(mtB, __shfl_xor_sync(0xffffffffu, mtB, 2));
        const float mnA = fmaxf(mA, mtA);
        const float mnB = fmaxf(mB, mtB);
        const float alA = exp2f((mA - mnA) * CE);
        const float alB = exp2f((mB - mnB) * CE);
        mA = mnA; mB = mnB;

        float suA = 0.f, suB = 0.f;
        #pragma unroll
        for (int nt = 0; nt < 8; nt++) {
            sc[nt][0] = exp2f((sc[nt][0] - mnA) * CE);
            sc[nt][1] = exp2f((sc[nt][1] - mnA) * CE);
            sc[nt][2] = exp2f((sc[nt][2] - mnB) * CE);
            sc[nt][3] = exp2f((sc[nt][3] - mnB) * CE);
            suA += sc[nt][0] + sc[nt][1];
            suB += sc[nt][2] + sc[nt][3];
        }
        suA += __shfl_xor_sync(0xffffffffu, suA, 1);
        suA += __shfl_xor_sync(0xffffffffu, suA, 2);
        suB += __shfl_xor_sync(0xffffffffu, suB, 1);
        suB += __shfl_xor_sync(0xffffffffu, suB, 2);
        lA = lA * alA + suA;
        lB = lB * alB + suB;
        #pragma unroll
        for (int nt = 0; nt < 8; nt++) {
            ctx[nt][0] *= alA; ctx[nt][1] *= alA;
            ctx[nt][2] *= alB; ctx[nt][3] *= alB;
        }

        // ---- pack P into A-fragments ----
        uint32_t ph[16];
        #pragma unroll
        for (int ks = 0; ks < 4; ks++) {
            const int u0 = 2*ks, u1 = 2*ks + 1;
            ph[ks*4+0] = hpack(sc[u0][0], sc[u0][1]);
            ph[ks*4+1] = hpack(sc[u0][2], sc[u0][3]);
            ph[ks*4+2] = hpack(sc[u1][0], sc[u1][1]);
            ph[ks*4+3] = hpack(sc[u1][2], sc[u1][3]);
        }

        // ---- ctx += P V ----
        #pragma unroll
        for (int nt = 0; nt < 8; nt++) {
            const int dhr = nt*8 + qrow;
            #pragma unroll
            for (int ks = 0; ks < 4; ks++) {
                uint32_t b_[2];
                const int wd = dhr*KROW + ks*8 + qk;
                b_[0] = Vt[wd]; b_[1] = Vt[wd + 4];
                mma_fp16(ctx[nt], ph + 4*ks, b_);
            }
        }
    }

    // ---- finalize & write fp16 concat-heads ----
    const float ivA = 1.0f / lA;
    const float ivB = 1.0f / lB;
    const int b_ = bh >> 4;
    const int h_ = bh & 15;
    #pragma unroll
    for (int nt = 0; nt < 8; nt++) {
        const int dh = nt*8 + 2*qk;
        uint32_t oA = hpack(ctx[nt][0]*ivA, ctx[nt][1]*ivA);
        uint32_t oB = hpack(ctx[nt][2]*ivB, ctx[nt][3]*ivB);
        *(uint32_t*)(g_atth + ((size_t)(b_*SS + rowA))*EE + h_*64 + dh) = oA;
        *(uint32_t*)(g_atth + ((size_t)(b_*SS + rowB))*EE + h_*64 + dh) = oB;
    }
}

// =====================================================================
// Kernel 4: LayerNorm (unchanged).
// =====================================================================
__global__ __launch_bounds__(256)
void ln_kernel(const float* __restrict__ gamma, const float* __restrict__ beta,
               float* __restrict__ out)
{
    const int row = blockIdx.x;
    const float* x = g_x + (size_t)row * EE;
    const int tid = threadIdx.x;

    float4 v = *(const float4*)(x + tid * 4);
    float s = v.x + v.y + v.z + v.w;
    float q = v.x*v.x + v.y*v.y + v.z*v.z + v.w*v.w;
    #pragma unroll
    for (int off = 16; off; off >>= 1) {
        s += __shfl_xor_sync(0xffffffffu, s, off);
        q += __shfl_xor_sync(0xffffffffu, q, off);
    }
    __shared__ float ssum[8], ssq[8], stats[2];
    const int w = tid >> 5;
    if ((tid & 31) == 0) { ssum[w] = s; ssq[w] = q; }
    __syncthreads();
    if (tid < 32) {
        float s2 = (tid < 8) ? ssum[tid] : 0.f;
        float q2 = (tid < 8) ? ssq[tid]  : 0.f;
        #pragma unroll
        for (int off = 4; off; off >>= 1) {
            s2 += __shfl_xor_sync(0xffffffffu, s2, off);
            q2 += __shfl_xor_sync(0xffffffffu, q2, off);
        }
        if (tid == 0) {
            float mu = s2 * (1.0f / EE);
            float var = q2 * (1.0f / EE) - mu * mu;
            stats[0] = mu;
            stats[1] = rsqrtf(var + 1e-5f);
        }
    }
    __syncthreads();
    const float mu = stats[0];
    const float r  = stats[1];

    float4 gv = *(const float4*)(gamma + tid * 4);
    float4 bv = *(const float4*)(beta  + tid * 4);
    float4 o;
    o.x = (v.x - mu) * r * gv.x + bv.x;
    o.y = (v.y - mu) * r * gv.y + bv.y;
    o.z = (v.z - mu) * r * gv.z + bv.z;
    o.w = (v.w - mu) * r * gv.w + bv.w;
    *(float4*)(out + (size_t)row * EE + tid * 4) = o;
}

// =====================================================================
extern "C" void kernel_launch(void* const* d_in, const int* in_sizes, int n_in,
                              void* d_out, int out_size)
{
    (void)in_sizes; (void)n_in; (void)out_size;
    const float* query = (const float*)d_in[0];
    const float* key_i = (const float*)d_in[1];
    const float* value = (const float*)d_in[2];
    // d_in[3] = mask (causal; hard-coded in kernel)
    const float* Wq_w = (const float*)d_in[4];
    const float* Wq_b = (const float*)d_in[5];
    const float* Wk_w = (const float*)d_in[6];
    const float* Wk_b = (const float*)d_in[7];
    const float* Wv_w = (const float*)d_in[8];
    const float* Wv_b = (const float*)d_in[9];
    const float* out_w = (const float*)d_in[10];
    const float* out_b = (const float*)d_in[11];
    const float* ln_g = (const float*)d_in[12];
    const float* ln_b = (const float*)d_in[13];
    float* out = (float*)d_out;

    const int SMEM_GEMM = 3 * 8192;              // 24576 B (3-stage)
    const int SMEM_ATTN = 2 * 64 * KROW * 4;     // 18432 B

    // 0. convert inputs + weights to fp16
    const int CVT_BLOCKS = (3*(MM*EE/4) + 4*(EE*EE/4)) / 256;   // 16384
    cvt_all<<<CVT_BLOCKS, 256>>>(query, key_i, value, Wq_w, Wk_w, Wv_w, out_w);

    // 1. QKV projections
    qkv_mma<<<dim3(EE/128, MM/128, 3), 128, SMEM_GEMM>>>(Wq_b, Wk_b, Wv_b);

    // 2. causal flash attention
    attn_mma<<<dim3(SS/64, BB*HH), 128, SMEM_ATTN>>>();

    // 3. output projection + residual
    proj_mma<<<dim3(EE/128, MM/128), 128, SMEM_GEMM>>>(query, out_b);

    // 4. LayerNorm
    ln_kernel<<<MM, 256>>>(ln_g, ln_b, out);
}